// round 2
// baseline (speedup 1.0000x reference)
#include <cuda_runtime.h>
#include <math.h>

#define N_NODES 100000
#define N_EDGES 3200000
#define N_GRAPH 64
#define AVG_LOG 3.4965075614664802f
#define BN_EPS 1e-5f
#define STD_EPS 1e-5f

// ---------------- scratch (device globals; no allocation allowed) ----------------
__device__ int   g_deg[N_NODES];
__device__ int   g_rowp[N_NODES + 1];
__device__ int   g_cur[N_NODES];
__device__ int   g_csr[N_EDGES];
__device__ float g_s1[N_NODES];
__device__ float g_s2[N_NODES];
__device__ float g_A[(size_t)N_NODES * 384];   // agg: [mean|min|max|std], F<=96
__device__ float g_hA[(size_t)N_NODES * 96];
__device__ float g_hB[(size_t)N_NODES * 96];
__device__ float g_part[128 * 192];            // BN partial sums
__device__ float g_scale[96];
__device__ float g_shift[96];
__device__ int   g_gstart[N_GRAPH + 1];
__device__ float g_z[N_GRAPH * 20];

// ---------------- CSR build ----------------
__global__ void k_zero() {
    int i = blockIdx.x * blockDim.x + threadIdx.x;
    if (i < N_NODES) { g_deg[i] = 0; g_cur[i] = 0; }
}

__global__ void k_hist(const int* __restrict__ dst) {
    int e = blockIdx.x * blockDim.x + threadIdx.x;
    if (e < N_EDGES) atomicAdd(&g_deg[dst[e]], 1);
}

__global__ void k_scan() {   // single-block exclusive scan of g_deg -> g_rowp
    __shared__ int warpsum[32];
    __shared__ int s_carry;
    int tid = threadIdx.x;
    int lane = tid & 31, wid = tid >> 5;
    if (tid == 0) s_carry = 0;
    __syncthreads();
    for (int base = 0; base < N_NODES; base += 1024) {
        int i = base + tid;
        int v = (i < N_NODES) ? g_deg[i] : 0;
        int x = v;
        #pragma unroll
        for (int off = 1; off < 32; off <<= 1) {
            int y = __shfl_up_sync(0xffffffffu, x, off);
            if (lane >= off) x += y;
        }
        if (lane == 31) warpsum[wid] = x;
        __syncthreads();
        if (wid == 0) {
            int w = warpsum[lane];
            #pragma unroll
            for (int off = 1; off < 32; off <<= 1) {
                int y = __shfl_up_sync(0xffffffffu, w, off);
                if (lane >= off) w += y;
            }
            warpsum[lane] = w;
        }
        __syncthreads();
        int excl = x - v + (wid > 0 ? warpsum[wid - 1] : 0);
        if (i < N_NODES) g_rowp[i] = s_carry + excl;
        __syncthreads();
        if (tid == 0) s_carry += warpsum[31];
        __syncthreads();
    }
    if (threadIdx.x == 0) g_rowp[N_NODES] = s_carry;
}

__global__ void k_scatter(const int* __restrict__ src, const int* __restrict__ dst) {
    int e = blockIdx.x * blockDim.x + threadIdx.x;
    if (e < N_EDGES) {
        int d = dst[e];
        int pos = atomicAdd(&g_cur[d], 1);
        g_csr[g_rowp[d] + pos] = src[e];
    }
}

// sort each adjacency list so the CSR (and thus all fp sums) is deterministic
__global__ void k_sort() {
    int n = blockIdx.x * blockDim.x + threadIdx.x;
    if (n >= N_NODES) return;
    int s = g_rowp[n], e = g_rowp[n + 1];
    int len = e - s;
    if (len <= 1) return;
    int loc[192];
    if (len <= 192) {
        for (int i = 0; i < len; i++) loc[i] = g_csr[s + i];
        for (int i = 1; i < len; i++) {
            int key = loc[i]; int j = i - 1;
            while (j >= 0 && loc[j] > key) { loc[j + 1] = loc[j]; j--; }
            loc[j + 1] = key;
        }
        for (int i = 0; i < len; i++) g_csr[s + i] = loc[i];
    } else {
        for (int i = 1; i < len; i++) {
            int key = g_csr[s + i]; int j = i - 1;
            while (j >= 0 && g_csr[s + j] > key) { g_csr[s + j + 1] = g_csr[s + j]; j--; }
            g_csr[s + j + 1] = key;
        }
    }
}

__global__ void k_s1s2() {
    int n = blockIdx.x * blockDim.x + threadIdx.x;
    if (n >= N_NODES) return;
    float degc = fmaxf((float)g_deg[n], 1.0f);
    float logd = logf(degc + 1.0f);
    g_s1[n] = logd / AVG_LOG;
    g_s2[n] = AVG_LOG / logd;
}

__global__ void k_bounds(const int* __restrict__ batch) {
    int i = blockIdx.x * blockDim.x + threadIdx.x;
    if (i >= N_NODES) return;
    if (i == 0) {
        for (int g = 0; g <= batch[0]; g++) g_gstart[g] = 0;
    } else {
        int b0 = batch[i - 1], b1 = batch[i];
        if (b1 != b0) for (int g = b0 + 1; g <= b1; g++) g_gstart[g] = i;
    }
    if (i == N_NODES - 1) {
        for (int g = batch[i] + 1; g <= N_GRAPH; g++) g_gstart[g] = N_NODES;
    }
}

// ---------------- aggregation: mean / min / max / std per node ----------------
template <int F>
__global__ void k_agg(const float* __restrict__ h) {
    __shared__ int nb[128];
    int n = blockIdx.x;
    int f = threadIdx.x;
    int s = g_rowp[n], e = g_rowp[n + 1];
    int deg = e - s;
    float sm = 0.0f, ss = 0.0f, mn = INFINITY, mx = -INFINITY;
    for (int c = s; c < e; c += 128) {
        int m = min(128, e - c);
        __syncthreads();
        for (int i = f; i < m; i += F) nb[i] = g_csr[c + i];
        __syncthreads();
        for (int j = 0; j < m; j++) {
            float v = h[(size_t)nb[j] * F + f];
            sm += v; ss += v * v;
            mn = fminf(mn, v); mx = fmaxf(mx, v);
        }
    }
    float degc = fmaxf((float)deg, 1.0f);
    float inv = 1.0f / degc;
    float mean = sm * inv;
    float var = ss * inv - mean * mean;
    float sd = sqrtf(fmaxf(var, 0.0f) + STD_EPS);
    if (deg == 0) { mn = 0.0f; mx = 0.0f; }
    size_t base = (size_t)n * (4 * F) + f;
    g_A[base]         = mean;
    g_A[base + F]     = mn;
    g_A[base + 2 * F] = mx;
    g_A[base + 3 * F] = sd;
}

// ---------------- fused PNA linear: out = [h | A | A*s1 | A*s2] @ W + b ----------------
template <int F, int FO, int TN, bool RELU>
__global__ void __launch_bounds__(256) k_gemm(const float* __restrict__ h,
                                              const float* __restrict__ W,
                                              const float* __restrict__ bias,
                                              float* __restrict__ out) {
    constexpr int BM = 128, BK = 32, TM = 8;
    constexpr int TX = FO / TN, TY = BM / TM;
    constexpr int NT = TX * TY;
    __shared__ float As[BK][BM + 1];
    __shared__ float Bs[BK][FO];
    int tid = threadIdx.x;
    int tx = tid % TX, ty = tid / TX;
    int nbase = blockIdx.x * BM;
    float acc[TM][TN];
    #pragma unroll
    for (int i = 0; i < TM; i++)
        #pragma unroll
        for (int j = 0; j < TN; j++) acc[i][j] = 0.0f;

    const int KTOT = 13 * F;
    for (int k0 = 0; k0 < KTOT; k0 += BK) {
        int seg, kloc0;
        if (k0 < F) { seg = 0; kloc0 = k0; }
        else { int t = k0 - F; seg = 1 + t / (4 * F); kloc0 = t % (4 * F); }
        for (int idx = tid; idx < BM * BK; idx += NT) {
            int r = idx >> 5, kk = idx & 31;
            int n = nbase + r;
            float v = 0.0f;
            if (n < N_NODES) {
                int kg = kloc0 + kk;
                if (seg == 0) v = h[(size_t)n * F + kg];
                else {
                    v = g_A[(size_t)n * (4 * F) + kg];
                    if (seg == 2) v *= g_s1[n];
                    else if (seg == 3) v *= g_s2[n];
                }
            }
            As[kk][r] = v;
        }
        for (int idx = tid; idx < BK * FO; idx += NT) {
            int kk = idx / FO, o = idx - kk * FO;
            Bs[kk][o] = W[(size_t)(k0 + kk) * FO + o];
        }
        __syncthreads();
        #pragma unroll 4
        for (int kk = 0; kk < BK; kk++) {
            float a[TM], bb[TN];
            #pragma unroll
            for (int im = 0; im < TM; im++) a[im] = As[kk][ty * TM + im];
            #pragma unroll
            for (int j = 0; j < TN; j++) bb[j] = Bs[kk][tx * TN + j];
            #pragma unroll
            for (int im = 0; im < TM; im++)
                #pragma unroll
                for (int j = 0; j < TN; j++)
                    acc[im][j] = fmaf(a[im], bb[j], acc[im][j]);
        }
        __syncthreads();
    }
    #pragma unroll
    for (int im = 0; im < TM; im++) {
        int n = nbase + ty * TM + im;
        if (n < N_NODES) {
            #pragma unroll
            for (int j = 0; j < TN; j++) {
                float r = acc[im][j] + bias[tx * TN + j];
                if (RELU) r = fmaxf(r, 0.0f);
                out[(size_t)n * FO + tx * TN + j] = r;
            }
        }
    }
}

// ---------------- batch norm (deterministic 2-stage stats) ----------------
template <int C>
__global__ void k_bnstats(const float* __restrict__ Y) {
    __shared__ float shs[4][C];
    __shared__ float shss[4][C];
    int c = threadIdx.x, y = threadIdx.y;
    int n0 = blockIdx.x * 1024;
    int n1 = min(N_NODES, n0 + 1024);
    float s = 0.0f, ss = 0.0f;
    for (int n = n0 + y; n < n1; n += 4) {
        float v = Y[(size_t)n * C + c];
        s += v; ss += v * v;
    }
    shs[y][c] = s; shss[y][c] = ss;
    __syncthreads();
    if (y == 0) {
        float S  = shs[0][c] + shs[1][c] + shs[2][c] + shs[3][c];
        float SS = shss[0][c] + shss[1][c] + shss[2][c] + shss[3][c];
        g_part[blockIdx.x * 2 * C + c]     = S;
        g_part[blockIdx.x * 2 * C + C + c] = SS;
    }
}

template <int C>
__global__ void k_bnfin(const float* __restrict__ g, const float* __restrict__ be, int nb) {
    int c = threadIdx.x;
    if (c >= C) return;
    float s = 0.0f, ss = 0.0f;
    for (int i = 0; i < nb; i++) {
        s  += g_part[i * 2 * C + c];
        ss += g_part[i * 2 * C + C + c];
    }
    float mu = s / (float)N_NODES;
    float var = ss / (float)N_NODES - mu * mu;
    float sc = g[c] * rsqrtf(var + BN_EPS);
    g_scale[c] = sc;
    g_shift[c] = be[c] - mu * sc;
}

template <int C, bool RELU>
__global__ void k_bnapply(float* __restrict__ Y) {
    int i = blockIdx.x * blockDim.x + threadIdx.x;
    if (i < N_NODES * C) {
        int c = i % C;
        float v = fmaf(Y[i], g_scale[c], g_shift[c]);
        if (RELU) v = fmaxf(v, 0.0f);
        Y[i] = v;
    }
}

// ---------------- pooling + classifier head ----------------
__global__ void k_pool(const float* __restrict__ h, float* __restrict__ outz, int write_out) {
    int g = blockIdx.x;
    int c = threadIdx.x, y = threadIdx.y;
    int s = g_gstart[g], e = g_gstart[g + 1];
    float acc = 0.0f;
    if (c < 20)
        for (int n = s + y; n < e; n += 8) acc += h[(size_t)n * 20 + c];
    __shared__ float sh[8][32];
    sh[y][c] = acc;
    __syncthreads();
    if (y == 0 && c < 20) {
        float S = 0.0f;
        #pragma unroll
        for (int k = 0; k < 8; k++) S += sh[k][c];
        float cntf = fmaxf((float)(e - s), 1.0f);
        float z = S / cntf;
        g_z[g * 20 + c] = z;
        if (write_out) outz[g * 20 + c] = z;
    }
}

__global__ void k_final(const float* __restrict__ wlin, const float* __restrict__ blin,
                        float* __restrict__ out) {
    int g = blockIdx.x;
    int o = threadIdx.x;
    float l = -INFINITY;
    if (o < 11) {
        float s = blin[o];
        for (int k = 0; k < 20; k++) s = fmaf(g_z[g * 20 + k], wlin[k * 11 + o], s);
        l = s;
    }
    float m = l;
    #pragma unroll
    for (int off = 16; off; off >>= 1) m = fmaxf(m, __shfl_xor_sync(0xffffffffu, m, off));
    float ex = (o < 11) ? expf(l - m) : 0.0f;
    float sum = ex;
    #pragma unroll
    for (int off = 16; off; off >>= 1) sum += __shfl_xor_sync(0xffffffffu, sum, off);
    if (o < 11) out[g * 11 + o] = ex / sum;
}

// ---------------- host ----------------
extern "C" void kernel_launch(void* const* d_in, const int* in_sizes, int n_in,
                              void* d_out, int out_size) {
    const float* x     = (const float*)d_in[0];
    const int*   ei    = (const int*)d_in[1];
    const int*   batch = (const int*)d_in[2];
    const float* w0 = (const float*)d_in[3];  const float* b0 = (const float*)d_in[4];
    const float* w1 = (const float*)d_in[5];  const float* b1 = (const float*)d_in[6];
    const float* w2 = (const float*)d_in[7];  const float* b2 = (const float*)d_in[8];
    const float* w3 = (const float*)d_in[9];  const float* b3 = (const float*)d_in[10];
    const float* g0 = (const float*)d_in[11]; const float* be0 = (const float*)d_in[12];
    const float* g1 = (const float*)d_in[13]; const float* be1 = (const float*)d_in[14];
    const float* g2 = (const float*)d_in[15]; const float* be2 = (const float*)d_in[16];
    const float* wlin = (const float*)d_in[17]; const float* blin = (const float*)d_in[18];
    float* out = (float*)d_out;

    const int* src = ei;
    const int* dst = ei + N_EDGES;

    float *hA, *hB;
    cudaGetSymbolAddress((void**)&hA, g_hA);
    cudaGetSymbolAddress((void**)&hB, g_hB);

    int nbE = (N_EDGES + 255) / 256;
    int nbN = (N_NODES + 255) / 256;

    // CSR + per-node scalers (edge structure is fixed, rebuilt deterministically each launch)
    k_zero<<<nbN, 256>>>();
    k_hist<<<nbE, 256>>>(dst);
    k_scan<<<1, 1024>>>();
    k_scatter<<<nbE, 256>>>(src, dst);
    k_sort<<<(N_NODES + 127) / 128, 128>>>();
    k_s1s2<<<nbN, 256>>>();
    k_bounds<<<nbN, 256>>>(batch);

    const int GB = (N_NODES + 127) / 128;   // GEMM blocks
    const int NBST = (N_NODES + 1023) / 1024;  // BN stat blocks

    // Layer 0: 64 -> 96, BN + relu
    k_agg<64><<<N_NODES, 64>>>(x);
    k_gemm<64, 96, 6, false><<<GB, 256>>>(x, w0, b0, hA);
    k_bnstats<96><<<NBST, dim3(96, 4)>>>(hA);
    k_bnfin<96><<<1, 96>>>(g0, be0, NBST);
    k_bnapply<96, true><<<(N_NODES * 96 + 255) / 256, 256>>>(hA);

    // Layer 1: 96 -> 64, BN + relu
    k_agg<96><<<N_NODES, 96>>>(hA);
    k_gemm<96, 64, 4, false><<<GB, 256>>>(hA, w1, b1, hB);
    k_bnstats<64><<<NBST, dim3(64, 4)>>>(hB);
    k_bnfin<64><<<1, 64>>>(g1, be1, NBST);
    k_bnapply<64, true><<<(N_NODES * 64 + 255) / 256, 256>>>(hB);

    // Layer 2: 64 -> 32, relu only (fused in GEMM epilogue)
    k_agg<64><<<N_NODES, 64>>>(hB);
    k_gemm<64, 32, 2, true><<<GB, 256>>>(hB, w2, b2, hA);

    // Layer 3: 32 -> 20, BN (no relu)
    k_agg<32><<<N_NODES, 32>>>(hA);
    k_gemm<32, 20, 2, false><<<GB, 160>>>(hA, w3, b3, hB);
    k_bnstats<20><<<NBST, dim3(20, 4)>>>(hB);
    k_bnfin<20><<<1, 20>>>(g2, be2, NBST);
    k_bnapply<20, false><<<(N_NODES * 20 + 255) / 256, 256>>>(hB);

    // Pool + head. Output layout: [softmax out (64x11) | z (64x20)]
    int write_z = (out_size >= 64 * 11 + 64 * 20) ? 1 : 0;
    k_pool<<<N_GRAPH, dim3(32, 8)>>>(hB, out + 64 * 11, write_z);
    k_final<<<N_GRAPH, 32>>>(wlin, blin, out);
}

// round 11
// speedup vs baseline: 1.3491x; 1.3491x over previous
#include <cuda_runtime.h>
#include <cuda_bf16.h>
#include <stdint.h>
#include <math.h>

#define N_NODES 100000
#define N_EDGES 3200000
#define N_GRAPH 64
#define AVG_LOG 3.4965075614664802f
#define BN_EPS 1e-5f
#define STD_EPS 1e-5f

// ---------------- scratch (device globals; no allocation allowed) ----------------
__device__ int   g_deg[N_NODES];
__device__ int   g_rowp[N_NODES + 1];
__device__ int   g_cur[N_NODES];
__device__ int   g_csr[N_EDGES];
__device__ float g_s1[N_NODES];
__device__ float g_s2[N_NODES];
__device__ float g_A[(size_t)N_NODES * 384];   // agg: [mean|min|max|std], F<=96
__device__ float g_hA[(size_t)N_NODES * 96];
__device__ float g_hB[(size_t)N_NODES * 96];
__device__ float g_part[128 * 192];            // BN partial sums
__device__ float g_scale[96];
__device__ float g_shift[96];
__device__ int   g_gstart[N_GRAPH + 1];
__device__ float g_z[N_GRAPH * 20];
__device__ __nv_bfloat16 g_Wth[96 * 1280];     // weight bf16-hi, [FOP][KP]
__device__ __nv_bfloat16 g_Wtl[96 * 1280];     // weight bf16-lo

// ---------------- helpers (base-ISA only: ldmatrix + mma.sync, no tcgen05) ----------------
__device__ __forceinline__ uint32_t smem_u32(const void* p) {
    uint32_t a;
    asm("{ .reg .u64 t; cvta.to.shared.u64 t, %1; cvt.u32.u64 %0, t; }" : "=r"(a) : "l"(p));
    return a;
}
__device__ __forceinline__ void ldsm4(uint32_t* r, uint32_t addr) {
    asm volatile("ldmatrix.sync.aligned.m8n8.x4.shared.b16 {%0,%1,%2,%3}, [%4];"
        : "=r"(r[0]), "=r"(r[1]), "=r"(r[2]), "=r"(r[3]) : "r"(addr));
}
__device__ __forceinline__ void mma16816(float* d, const uint32_t* a, uint32_t b0, uint32_t b1) {
    asm volatile(
        "mma.sync.aligned.m16n8k16.row.col.f32.bf16.bf16.f32 "
        "{%0,%1,%2,%3}, {%4,%5,%6,%7}, {%8,%9}, {%0,%1,%2,%3};"
        : "+f"(d[0]), "+f"(d[1]), "+f"(d[2]), "+f"(d[3])
        : "r"(a[0]), "r"(a[1]), "r"(a[2]), "r"(a[3]), "r"(b0), "r"(b1));
}
__device__ __forceinline__ void sts128(uint32_t a, uint32_t x, uint32_t y, uint32_t z, uint32_t w) {
    asm volatile("st.shared.v4.b32 [%0], {%1,%2,%3,%4};" :: "r"(a), "r"(x), "r"(y), "r"(z), "r"(w) : "memory");
}
__device__ __forceinline__ uint32_t swz(uint32_t off) { return off ^ ((off >> 3) & 0x70); }
__device__ __forceinline__ uint32_t pack2(__nv_bfloat16 a, __nv_bfloat16 b) {
    return (uint32_t)__bfloat16_as_ushort(a) | ((uint32_t)__bfloat16_as_ushort(b) << 16);
}

// ---------------- CSR build ----------------
__global__ void k_zero() {
    int i = blockIdx.x * blockDim.x + threadIdx.x;
    if (i < N_NODES) { g_deg[i] = 0; g_cur[i] = 0; }
}
__global__ void k_hist(const int* __restrict__ dst) {
    int e = blockIdx.x * blockDim.x + threadIdx.x;
    if (e < N_EDGES) atomicAdd(&g_deg[dst[e]], 1);
}
__global__ void k_scan() {
    __shared__ int warpsum[32];
    __shared__ int s_carry;
    int tid = threadIdx.x;
    int lane = tid & 31, wid = tid >> 5;
    if (tid == 0) s_carry = 0;
    __syncthreads();
    for (int base = 0; base < N_NODES; base += 1024) {
        int i = base + tid;
        int v = (i < N_NODES) ? g_deg[i] : 0;
        int x = v;
        #pragma unroll
        for (int off = 1; off < 32; off <<= 1) {
            int y = __shfl_up_sync(0xffffffffu, x, off);
            if (lane >= off) x += y;
        }
        if (lane == 31) warpsum[wid] = x;
        __syncthreads();
        if (wid == 0) {
            int w = warpsum[lane];
            #pragma unroll
            for (int off = 1; off < 32; off <<= 1) {
                int y = __shfl_up_sync(0xffffffffu, w, off);
                if (lane >= off) w += y;
            }
            warpsum[lane] = w;
        }
        __syncthreads();
        int excl = x - v + (wid > 0 ? warpsum[wid - 1] : 0);
        if (i < N_NODES) g_rowp[i] = s_carry + excl;
        __syncthreads();
        if (tid == 0) s_carry += warpsum[31];
        __syncthreads();
    }
    if (threadIdx.x == 0) g_rowp[N_NODES] = s_carry;
}
__global__ void k_scatter(const int* __restrict__ src, const int* __restrict__ dst) {
    int e = blockIdx.x * blockDim.x + threadIdx.x;
    if (e < N_EDGES) {
        int d = dst[e];
        int pos = atomicAdd(&g_cur[d], 1);
        g_csr[g_rowp[d] + pos] = src[e];
    }
}
__global__ void k_s1s2() {
    int n = blockIdx.x * blockDim.x + threadIdx.x;
    if (n >= N_NODES) return;
    float degc = fmaxf((float)g_deg[n], 1.0f);
    float logd = logf(degc + 1.0f);
    g_s1[n] = logd / AVG_LOG;
    g_s2[n] = AVG_LOG / logd;
}
__global__ void k_bounds(const int* __restrict__ batch) {
    int i = blockIdx.x * blockDim.x + threadIdx.x;
    if (i >= N_NODES) return;
    if (i == 0) {
        for (int g = 0; g <= batch[0]; g++) g_gstart[g] = 0;
    } else {
        int b0 = batch[i - 1], b1 = batch[i];
        if (b1 != b0) for (int g = b0 + 1; g <= b1; g++) g_gstart[g] = i;
    }
    if (i == N_NODES - 1) {
        for (int g = batch[i] + 1; g <= N_GRAPH; g++) g_gstart[g] = N_NODES;
    }
}

// ---------------- aggregation: mean / min / max / std per node ----------------
template <int F>
__global__ void k_agg(const float* __restrict__ h) {
    __shared__ int nb[128];
    int n = blockIdx.x;
    int f = threadIdx.x;
    int s = g_rowp[n], e = g_rowp[n + 1];
    int deg = e - s;
    float sm = 0.0f, ss = 0.0f, mn = INFINITY, mx = -INFINITY;
    for (int c = s; c < e; c += 128) {
        int m = min(128, e - c);
        __syncthreads();
        for (int i = f; i < m; i += F) nb[i] = g_csr[c + i];
        __syncthreads();
        for (int j = 0; j < m; j++) {
            float v = h[(size_t)nb[j] * F + f];
            sm += v; ss += v * v;
            mn = fminf(mn, v); mx = fmaxf(mx, v);
        }
    }
    float degc = fmaxf((float)deg, 1.0f);
    float inv = 1.0f / degc;
    float mean = sm * inv;
    float var = ss * inv - mean * mean;
    float sd = sqrtf(fmaxf(var, 0.0f) + STD_EPS);
    if (deg == 0) { mn = 0.0f; mx = 0.0f; }
    size_t base = (size_t)n * (4 * F) + f;
    g_A[base]         = mean;
    g_A[base + F]     = mn;
    g_A[base + 2 * F] = mx;
    g_A[base + 3 * F] = sd;
}

// ---------------- weight pre-split: W[13F,FO] -> Wt[FOP][KP] bf16 hi/lo ----------------
__global__ void k_wsplit(const float* __restrict__ W, int F, int FO, int FOP, int KP) {
    int K13 = 13 * F;
    int total = FOP * KP;
    int idx = blockIdx.x * blockDim.x + threadIdx.x;
    if (idx >= total) return;
    int o = idx / KP, k = idx - o * KP;
    float v = 0.0f;
    if (o < FO && k < K13) v = W[(size_t)k * FO + o];
    __nv_bfloat16 hi = __float2bfloat16(v);
    float r = v - __bfloat162float(hi);
    g_Wth[idx] = hi;
    g_Wtl[idx] = __float2bfloat16(r);
}

// ---------------- mma.sync fused PNA GEMM ----------------
// out[n][o] = ([h | agg | agg*s1 | agg*s2] @ W)[n][o] + bias[o]  (optional relu)
// A' built on the fly into SW128 smem as bf16 hi/lo; 3-pass hi/lo mma for ~fp32 accuracy.
template <int NT>   // NT = FOP/8 output tiles (FOP = NT*8 >= FO)
__global__ __launch_bounds__(256) void k_mma_gemm(
    const float* __restrict__ h,
    const __nv_bfloat16* __restrict__ Wth, const __nv_bfloat16* __restrict__ Wtl,
    const float* __restrict__ bias, float* __restrict__ out,
    int F, int FO, int KP, int relu)
{
    const int K13 = 13 * F;
    const int NCH = KP >> 6;          // 64-wide k chunks
    extern __shared__ char smem_raw[];
    uint32_t base = (smem_u32(smem_raw) + 1023u) & ~1023u;
    uint32_t AHI = base;              // 128 rows x 128B
    uint32_t ALO = AHI + 16384;
    uint32_t BHI = ALO + 16384;       // NT*8 rows x 128B
    uint32_t BLO = BHI + (uint32_t)(NT * 1024);

    int tid = threadIdx.x;
    int wid = tid >> 5, lane = tid & 31;
    int nbase = blockIdx.x * 128;

    float acc[NT][4];
    #pragma unroll
    for (int t = 0; t < NT; t++) {
        acc[t][0] = 0.f; acc[t][1] = 0.f; acc[t][2] = 0.f; acc[t][3] = 0.f;
    }

    // ldmatrix lane addressing: r16 = row-within-16, c4 selects k halves
    int r16 = lane & 15;
    int c4 = lane >> 4;

    for (int c = 0; c < NCH; c++) {
        __syncthreads();
        // ---- build A' tile: 128 rows x 64 k, fp32 -> (scaled) bf16 hi/lo ----
        for (int p = tid; p < 1024; p += 256) {
            int row = p >> 3, g = p & 7;
            int n = nbase + row;
            int k = c * 64 + g * 8;
            float4 v0 = make_float4(0.f, 0.f, 0.f, 0.f), v1 = v0;
            if (n < N_NODES && k < K13) {
                const float* sp;
                float sc = 1.0f;
                if (k < F) {
                    sp = h + (size_t)n * F + k;
                } else if (k < 5 * F) {
                    sp = g_A + (size_t)n * 4 * F + (k - F);
                } else if (k < 9 * F) {
                    sp = g_A + (size_t)n * 4 * F + (k - 5 * F);
                    sc = g_s1[n];
                } else {
                    sp = g_A + (size_t)n * 4 * F + (k - 9 * F);
                    sc = g_s2[n];
                }
                v0 = *(const float4*)sp;
                v1 = *(const float4*)(sp + 4);
                v0.x *= sc; v0.y *= sc; v0.z *= sc; v0.w *= sc;
                v1.x *= sc; v1.y *= sc; v1.z *= sc; v1.w *= sc;
            }
            float vv[8];
            vv[0] = v0.x; vv[1] = v0.y; vv[2] = v0.z; vv[3] = v0.w;
            vv[4] = v1.x; vv[5] = v1.y; vv[6] = v1.z; vv[7] = v1.w;
            uint32_t hi4[4], lo4[4];
            #pragma unroll
            for (int i = 0; i < 4; i++) {
                __nv_bfloat16 h0 = __float2bfloat16(vv[2 * i]);
                __nv_bfloat16 h1 = __float2bfloat16(vv[2 * i + 1]);
                float r0 = vv[2 * i] - __bfloat162float(h0);
                float r1 = vv[2 * i + 1] - __bfloat162float(h1);
                hi4[i] = pack2(h0, h1);
                lo4[i] = pack2(__float2bfloat16(r0), __float2bfloat16(r1));
            }
            uint32_t off = swz((uint32_t)(row * 128 + g * 16));
            sts128(AHI + off, hi4[0], hi4[1], hi4[2], hi4[3]);
            sts128(ALO + off, lo4[0], lo4[1], lo4[2], lo4[3]);
        }
        // ---- B tile: NT*8 rows x 64 k from pre-split weights ----
        for (int p = tid; p < NT * 8 * 8; p += 256) {
            int row = p >> 3, g = p & 7;
            int k = c * 64 + g * 8;
            uint4 vh = *(const uint4*)(Wth + (size_t)row * KP + k);
            uint4 vl = *(const uint4*)(Wtl + (size_t)row * KP + k);
            uint32_t off = swz((uint32_t)(row * 128 + g * 16));
            sts128(BHI + off, vh.x, vh.y, vh.z, vh.w);
            sts128(BLO + off, vl.x, vl.y, vl.z, vl.w);
        }
        __syncthreads();
        // ---- compute: 4 k16-steps per chunk ----
        #pragma unroll
        for (int ks = 0; ks < 4; ks++) {
            uint32_t aoff = swz((uint32_t)((wid * 16 + r16) * 128 + ks * 32 + c4 * 16));
            uint32_t ah[4], al[4];
            ldsm4(ah, AHI + aoff);
            ldsm4(al, ALO + aoff);
            #pragma unroll
            for (int nt2 = 0; nt2 < NT / 2; nt2++) {
                uint32_t boff = swz((uint32_t)((nt2 * 16 + r16) * 128 + ks * 32 + c4 * 16));
                uint32_t bh[4], bl[4];
                ldsm4(bh, BHI + boff);
                ldsm4(bl, BLO + boff);
                int t0 = nt2 * 2, t1 = t0 + 1;
                mma16816(acc[t0], ah, bh[0], bh[2]);
                mma16816(acc[t0], ah, bl[0], bl[2]);
                mma16816(acc[t0], al, bh[0], bh[2]);
                mma16816(acc[t1], ah, bh[1], bh[3]);
                mma16816(acc[t1], ah, bl[1], bl[3]);
                mma16816(acc[t1], al, bh[1], bh[3]);
            }
        }
    }
    // ---- epilogue: bias + optional relu, registers -> gmem ----
    int n0 = nbase + wid * 16 + (lane >> 2);
    int n1 = n0 + 8;
    int cb = (lane & 3) * 2;
    #pragma unroll
    for (int t = 0; t < NT; t++) {
        int col = t * 8 + cb;
        if (col < FO) {
            float b0 = bias[col];
            float b1 = (col + 1 < FO) ? bias[col + 1] : 0.f;
            if (n0 < N_NODES) {
                float u0 = acc[t][0] + b0;
                float u1 = acc[t][1] + b1;
                if (relu) { u0 = fmaxf(u0, 0.f); u1 = fmaxf(u1, 0.f); }
                out[(size_t)n0 * FO + col] = u0;
                if (col + 1 < FO) out[(size_t)n0 * FO + col + 1] = u1;
            }
            if (n1 < N_NODES) {
                float u2 = acc[t][2] + b0;
                float u3 = acc[t][3] + b1;
                if (relu) { u2 = fmaxf(u2, 0.f); u3 = fmaxf(u3, 0.f); }
                out[(size_t)n1 * FO + col] = u2;
                if (col + 1 < FO) out[(size_t)n1 * FO + col + 1] = u3;
            }
        }
    }
}

// ---------------- batch norm (deterministic 2-stage stats) ----------------
template <int C>
__global__ void k_bnstats(const float* __restrict__ Y) {
    __shared__ float shs[4][C];
    __shared__ float shss[4][C];
    int c = threadIdx.x, y = threadIdx.y;
    int n0 = blockIdx.x * 1024;
    int n1 = min(N_NODES, n0 + 1024);
    float s = 0.0f, ss = 0.0f;
    for (int n = n0 + y; n < n1; n += 4) {
        float v = Y[(size_t)n * C + c];
        s += v; ss += v * v;
    }
    shs[y][c] = s; shss[y][c] = ss;
    __syncthreads();
    if (y == 0) {
        float S  = shs[0][c] + shs[1][c] + shs[2][c] + shs[3][c];
        float SS = shss[0][c] + shss[1][c] + shss[2][c] + shss[3][c];
        g_part[blockIdx.x * 2 * C + c]     = S;
        g_part[blockIdx.x * 2 * C + C + c] = SS;
    }
}
template <int C>
__global__ void k_bnfin(const float* __restrict__ g, const float* __restrict__ be, int nb) {
    int c = threadIdx.x;
    if (c >= C) return;
    float s = 0.0f, ss = 0.0f;
    for (int i = 0; i < nb; i++) {
        s  += g_part[i * 2 * C + c];
        ss += g_part[i * 2 * C + C + c];
    }
    float mu = s / (float)N_NODES;
    float var = ss / (float)N_NODES - mu * mu;
    float sc = g[c] * rsqrtf(var + BN_EPS);
    g_scale[c] = sc;
    g_shift[c] = be[c] - mu * sc;
}
template <int C, bool RELU>
__global__ void k_bnapply(float* __restrict__ Y) {
    int i = blockIdx.x * blockDim.x + threadIdx.x;
    if (i < N_NODES * C) {
        int c = i % C;
        float v = fmaf(Y[i], g_scale[c], g_shift[c]);
        if (RELU) v = fmaxf(v, 0.0f);
        Y[i] = v;
    }
}

// ---------------- pooling + classifier head ----------------
__global__ void k_pool(const float* __restrict__ h, float* __restrict__ outz, int write_out) {
    int g = blockIdx.x;
    int c = threadIdx.x, y = threadIdx.y;
    int s = g_gstart[g], e = g_gstart[g + 1];
    float acc = 0.0f;
    if (c < 20)
        for (int n = s + y; n < e; n += 8) acc += h[(size_t)n * 20 + c];
    __shared__ float sh[8][32];
    sh[y][c] = acc;
    __syncthreads();
    if (y == 0 && c < 20) {
        float S = 0.0f;
        #pragma unroll
        for (int k = 0; k < 8; k++) S += sh[k][c];
        float cntf = fmaxf((float)(e - s), 1.0f);
        float z = S / cntf;
        g_z[g * 20 + c] = z;
        if (write_out) outz[g * 20 + c] = z;
    }
}
__global__ void k_final(const float* __restrict__ wlin, const float* __restrict__ blin,
                        float* __restrict__ out) {
    int g = blockIdx.x;
    int o = threadIdx.x;
    float l = -INFINITY;
    if (o < 11) {
        float s = blin[o];
        for (int k = 0; k < 20; k++) s = fmaf(g_z[g * 20 + k], wlin[k * 11 + o], s);
        l = s;
    }
    float m = l;
    #pragma unroll
    for (int off = 16; off; off >>= 1) m = fmaxf(m, __shfl_xor_sync(0xffffffffu, m, off));
    float ex = (o < 11) ? expf(l - m) : 0.0f;
    float sum = ex;
    #pragma unroll
    for (int off = 16; off; off >>= 1) sum += __shfl_xor_sync(0xffffffffu, sum, off);
    if (o < 11) out[g * 11 + o] = ex / sum;
}

// ---------------- host ----------------
extern "C" void kernel_launch(void* const* d_in, const int* in_sizes, int n_in,
                              void* d_out, int out_size) {
    const float* x     = (const float*)d_in[0];
    const int*   ei    = (const int*)d_in[1];
    const int*   batch = (const int*)d_in[2];
    const float* w0 = (const float*)d_in[3];  const float* b0 = (const float*)d_in[4];
    const float* w1 = (const float*)d_in[5];  const float* b1 = (const float*)d_in[6];
    const float* w2 = (const float*)d_in[7];  const float* b2 = (const float*)d_in[8];
    const float* w3 = (const float*)d_in[9];  const float* b3 = (const float*)d_in[10];
    const float* g0 = (const float*)d_in[11]; const float* be0 = (const float*)d_in[12];
    const float* g1 = (const float*)d_in[13]; const float* be1 = (const float*)d_in[14];
    const float* g2 = (const float*)d_in[15]; const float* be2 = (const float*)d_in[16];
    const float* wlin = (const float*)d_in[17]; const float* blin = (const float*)d_in[18];
    float* out = (float*)d_out;

    const int* src = ei;
    const int* dst = ei + N_EDGES;

    float *hA, *hB;
    __nv_bfloat16 *wth, *wtl;
    cudaGetSymbolAddress((void**)&hA, g_hA);
    cudaGetSymbolAddress((void**)&hB, g_hB);
    cudaGetSymbolAddress((void**)&wth, g_Wth);
    cudaGetSymbolAddress((void**)&wtl, g_Wtl);

    int nbE = (N_EDGES + 255) / 256;
    int nbN = (N_NODES + 255) / 256;

    // dynamic smem: 1024 pad + 32KB A(hi/lo) + 2*NT*1024 B(hi/lo)
    const int SM12 = 1024 + 32768 + 2 * 12 * 1024;  // 58368
    const int SM8  = 1024 + 32768 + 2 * 8 * 1024;
    const int SM4  = 1024 + 32768 + 2 * 4 * 1024;
    typedef void (*gemm_fn)(const float*, const __nv_bfloat16*, const __nv_bfloat16*,
                            const float*, float*, int, int, int, int);
    gemm_fn f12 = k_mma_gemm<12>;
    gemm_fn f8  = k_mma_gemm<8>;
    gemm_fn f4  = k_mma_gemm<4>;
    cudaFuncSetAttribute((const void*)f12, cudaFuncAttributeMaxDynamicSharedMemorySize, SM12);
    cudaFuncSetAttribute((const void*)f8,  cudaFuncAttributeMaxDynamicSharedMemorySize, SM8);
    cudaFuncSetAttribute((const void*)f4,  cudaFuncAttributeMaxDynamicSharedMemorySize, SM4);

    // CSR + per-node scalers (unsorted adjacency: fp reorder noise ~1e-7 << 1e-3 tol)
    k_zero<<<nbN, 256>>>();
    k_hist<<<nbE, 256>>>(dst);
    k_scan<<<1, 1024>>>();
    k_scatter<<<nbE, 256>>>(src, dst);
    k_s1s2<<<nbN, 256>>>();
    k_bounds<<<nbN, 256>>>(batch);

    const int GB = (N_NODES + 127) / 128;      // 782
    const int NBST = (N_NODES + 1023) / 1024;

    // KP = 13F padded to 64
    const int KP0 = ((13 * 64 + 63) / 64) * 64;   // 832
    const int KP1 = ((13 * 96 + 63) / 64) * 64;   // 1280
    const int KP2 = KP0;                           // 832
    const int KP3 = ((13 * 32 + 63) / 64) * 64;   // 448

    // Layer 0: 64 -> 96, BN + relu
    k_wsplit<<<(96 * KP0 + 255) / 256, 256>>>(w0, 64, 96, 96, KP0);
    k_agg<64><<<N_NODES, 64>>>(x);
    k_mma_gemm<12><<<GB, 256, SM12>>>(x, wth, wtl, b0, hA, 64, 96, KP0, 0);
    k_bnstats<96><<<NBST, dim3(96, 4)>>>(hA);
    k_bnfin<96><<<1, 96>>>(g0, be0, NBST);
    k_bnapply<96, true><<<(N_NODES * 96 + 255) / 256, 256>>>(hA);

    // Layer 1: 96 -> 64, BN + relu
    k_wsplit<<<(64 * KP1 + 255) / 256, 256>>>(w1, 96, 64, 64, KP1);
    k_agg<96><<<N_NODES, 96>>>(hA);
    k_mma_gemm<8><<<GB, 256, SM8>>>(hA, wth, wtl, b1, hB, 96, 64, KP1, 0);
    k_bnstats<64><<<NBST, dim3(64, 4)>>>(hB);
    k_bnfin<64><<<1, 64>>>(g1, be1, NBST);
    k_bnapply<64, true><<<(N_NODES * 64 + 255) / 256, 256>>>(hB);

    // Layer 2: 64 -> 32, relu (fused in epilogue)
    k_wsplit<<<(32 * KP2 + 255) / 256, 256>>>(w2, 64, 32, 32, KP2);
    k_agg<64><<<N_NODES, 64>>>(hB);
    k_mma_gemm<4><<<GB, 256, SM4>>>(hB, wth, wtl, b2, hA, 64, 32, KP2, 1);

    // Layer 3: 32 -> 20, BN (no relu)
    k_wsplit<<<(32 * KP3 + 255) / 256, 256>>>(w3, 32, 20, 32, KP3);
    k_agg<32><<<N_NODES, 32>>>(hA);
    k_mma_gemm<4><<<GB, 256, SM4>>>(hA, wth, wtl, b3, hB, 32, 20, KP3, 0);
    k_bnstats<20><<<NBST, dim3(20, 4)>>>(hB);
    k_bnfin<20><<<1, 20>>>(g2, be2, NBST);
    k_bnapply<20, false><<<(N_NODES * 20 + 255) / 256, 256>>>(hB);

    // Pool + head. Output layout: [softmax out (64x11) | z (64x20)]
    int write_z = (out_size >= 64 * 11 + 64 * 20) ? 1 : 0;
    k_pool<<<N_GRAPH, dim3(32, 8)>>>(hB, out + 64 * 11, write_z);
    k_final<<<N_GRAPH, 32>>>(wlin, blin, out);
}

// round 12
// speedup vs baseline: 1.7377x; 1.2880x over previous
#include <cuda_runtime.h>
#include <cuda_bf16.h>
#include <stdint.h>
#include <math.h>

#define N_NODES 100000
#define N_EDGES 3200000
#define N_GRAPH 64
#define AVG_LOG 3.4965075614664802f
#define BN_EPS 1e-5f
#define STD_EPS 1e-5f

// ---------------- scratch (device globals; no allocation allowed) ----------------
__device__ int   g_deg[N_NODES];
__device__ int   g_rowp[N_NODES + 1];
__device__ int   g_cur[N_NODES];
__device__ int   g_csr[N_EDGES];
__device__ float g_s1[N_NODES];
__device__ float g_s2[N_NODES];
__device__ float g_A[(size_t)N_NODES * 384];   // agg: [mean|min|max|std], F<=96
__device__ float g_hA[(size_t)N_NODES * 96];
__device__ float g_hB[(size_t)N_NODES * 96];
__device__ float g_part[128 * 192];            // BN partial sums
__device__ float g_scale[96];
__device__ float g_shift[96];
__device__ int   g_gstart[N_GRAPH + 1];
__device__ float g_z[N_GRAPH * 20];
__device__ __nv_bfloat16 g_Wth[3 * 96 * 512];  // weight bf16-hi, [3*FOP][K5P]
__device__ __nv_bfloat16 g_Wtl[3 * 96 * 512];  // weight bf16-lo

// ---------------- helpers (base-ISA only: ldmatrix + mma.sync) ----------------
__device__ __forceinline__ uint32_t smem_u32(const void* p) {
    uint32_t a;
    asm("{ .reg .u64 t; cvta.to.shared.u64 t, %1; cvt.u32.u64 %0, t; }" : "=r"(a) : "l"(p));
    return a;
}
__device__ __forceinline__ void ldsm4(uint32_t* r, uint32_t addr) {
    asm volatile("ldmatrix.sync.aligned.m8n8.x4.shared.b16 {%0,%1,%2,%3}, [%4];"
        : "=r"(r[0]), "=r"(r[1]), "=r"(r[2]), "=r"(r[3]) : "r"(addr));
}
__device__ __forceinline__ void mma16816(float* d, const uint32_t* a, uint32_t b0, uint32_t b1) {
    asm volatile(
        "mma.sync.aligned.m16n8k16.row.col.f32.bf16.bf16.f32 "
        "{%0,%1,%2,%3}, {%4,%5,%6,%7}, {%8,%9}, {%0,%1,%2,%3};"
        : "+f"(d[0]), "+f"(d[1]), "+f"(d[2]), "+f"(d[3])
        : "r"(a[0]), "r"(a[1]), "r"(a[2]), "r"(a[3]), "r"(b0), "r"(b1));
}
__device__ __forceinline__ void sts128(uint32_t a, uint32_t x, uint32_t y, uint32_t z, uint32_t w) {
    asm volatile("st.shared.v4.b32 [%0], {%1,%2,%3,%4};" :: "r"(a), "r"(x), "r"(y), "r"(z), "r"(w) : "memory");
}
__device__ __forceinline__ uint32_t swz(uint32_t off) { return off ^ ((off >> 3) & 0x70); }
__device__ __forceinline__ uint32_t pack2(__nv_bfloat16 a, __nv_bfloat16 b) {
    return (uint32_t)__bfloat16_as_ushort(a) | ((uint32_t)__bfloat16_as_ushort(b) << 16);
}

// ---------------- CSR build ----------------
__global__ void k_zero() {
    int i = blockIdx.x * blockDim.x + threadIdx.x;
    if (i < N_NODES) { g_deg[i] = 0; g_cur[i] = 0; }
}
__global__ void k_hist(const int* __restrict__ dst) {
    int e = blockIdx.x * blockDim.x + threadIdx.x;
    if (e < N_EDGES) atomicAdd(&g_deg[dst[e]], 1);
}
__global__ void k_scan() {
    __shared__ int warpsum[32];
    __shared__ int s_carry;
    int tid = threadIdx.x;
    int lane = tid & 31, wid = tid >> 5;
    if (tid == 0) s_carry = 0;
    __syncthreads();
    for (int base = 0; base < N_NODES; base += 1024) {
        int i = base + tid;
        int v = (i < N_NODES) ? g_deg[i] : 0;
        int x = v;
        #pragma unroll
        for (int off = 1; off < 32; off <<= 1) {
            int y = __shfl_up_sync(0xffffffffu, x, off);
            if (lane >= off) x += y;
        }
        if (lane == 31) warpsum[wid] = x;
        __syncthreads();
        if (wid == 0) {
            int w = warpsum[lane];
            #pragma unroll
            for (int off = 1; off < 32; off <<= 1) {
                int y = __shfl_up_sync(0xffffffffu, w, off);
                if (lane >= off) w += y;
            }
            warpsum[lane] = w;
        }
        __syncthreads();
        int excl = x - v + (wid > 0 ? warpsum[wid - 1] : 0);
        if (i < N_NODES) g_rowp[i] = s_carry + excl;
        __syncthreads();
        if (tid == 0) s_carry += warpsum[31];
        __syncthreads();
    }
    if (threadIdx.x == 0) g_rowp[N_NODES] = s_carry;
}
__global__ void k_scatter(const int* __restrict__ src, const int* __restrict__ dst) {
    int e = blockIdx.x * blockDim.x + threadIdx.x;
    if (e < N_EDGES) {
        int d = dst[e];
        int pos = atomicAdd(&g_cur[d], 1);
        g_csr[g_rowp[d] + pos] = src[e];
    }
}
__global__ void k_s1s2() {
    int n = blockIdx.x * blockDim.x + threadIdx.x;
    if (n >= N_NODES) return;
    float degc = fmaxf((float)g_deg[n], 1.0f);
    float logd = logf(degc + 1.0f);
    g_s1[n] = logd / AVG_LOG;
    g_s2[n] = AVG_LOG / logd;
}
__global__ void k_bounds(const int* __restrict__ batch) {
    int i = blockIdx.x * blockDim.x + threadIdx.x;
    if (i >= N_NODES) return;
    if (i == 0) {
        for (int g = 0; g <= batch[0]; g++) g_gstart[g] = 0;
    } else {
        int b0 = batch[i - 1], b1 = batch[i];
        if (b1 != b0) for (int g = b0 + 1; g <= b1; g++) g_gstart[g] = i;
    }
    if (i == N_NODES - 1) {
        for (int g = batch[i] + 1; g <= N_GRAPH; g++) g_gstart[g] = N_NODES;
    }
}

// ---------------- aggregation: mean / min / max / std per node ----------------
template <int F>
__global__ void k_agg(const float* __restrict__ h) {
    __shared__ int nb[128];
    int n = blockIdx.x;
    int f = threadIdx.x;
    int s = g_rowp[n], e = g_rowp[n + 1];
    int deg = e - s;
    float sm = 0.0f, ss = 0.0f, mn = INFINITY, mx = -INFINITY;
    for (int c = s; c < e; c += 128) {
        int m = min(128, e - c);
        __syncthreads();
        for (int i = f; i < m; i += F) nb[i] = g_csr[c + i];
        __syncthreads();
        for (int j = 0; j < m; j++) {
            float v = h[(size_t)nb[j] * F + f];
            sm += v; ss += v * v;
            mn = fminf(mn, v); mx = fmaxf(mx, v);
        }
    }
    float degc = fmaxf((float)deg, 1.0f);
    float inv = 1.0f / degc;
    float mean = sm * inv;
    float var = ss * inv - mean * mean;
    float sd = sqrtf(fmaxf(var, 0.0f) + STD_EPS);
    if (deg == 0) { mn = 0.0f; mx = 0.0f; }
    size_t base = (size_t)n * (4 * F) + f;
    g_A[base]         = mean;
    g_A[base + F]     = mn;
    g_A[base + 2 * F] = mx;
    g_A[base + 3 * F] = sd;
}

// ---------------- weight pre-split: W[13F,FO] -> 3 slabs [3*FOP][K5P] bf16 hi/lo ----
// slab j=0: B[o][k] = W[k][o], k in [0,5F)      (self + raw agg)
// slab j=1: k<F -> 0, else W[4F+k][o]           (agg block of W's s1 section)
// slab j=2: k<F -> 0, else W[8F+k][o]           (agg block of W's s2 section)
__global__ void k_wsplit(const float* __restrict__ W, int F, int FO, int FOP, int K5P) {
    int K5 = 5 * F;
    int total = 3 * FOP * K5P;
    int idx = blockIdx.x * blockDim.x + threadIdx.x;
    if (idx >= total) return;
    int row = idx / K5P, k = idx - row * K5P;
    int j = row / FOP, o = row - j * FOP;
    float v = 0.0f;
    if (o < FO && k < K5) {
        if (j == 0) v = W[(size_t)k * FO + o];
        else if (k >= F) v = W[(size_t)(4 * F * j + k) * FO + o];
    }
    __nv_bfloat16 hi = __float2bfloat16(v);
    float r = v - __bfloat162float(hi);
    g_Wth[idx] = hi;
    g_Wtl[idx] = __float2bfloat16(r);
}

// ---------------- mma.sync fused PNA GEMM (3 accumulator sets) ----------------
// A' = [h | agg] (5F wide). acc0 = A'@W0', acc1 = agg@W2, acc2 = agg@W3.
// out = acc0 + s1*acc1 + s2*acc2 + bias (optional relu). 3-pass bf16 hi/lo per product.
template <int NT, int CS>   // NT = cols/8 per warp; CS = column split (1 or 2)
__global__ __launch_bounds__(256) void k_mma_gemm(
    const float* __restrict__ h,
    const __nv_bfloat16* __restrict__ Wth, const __nv_bfloat16* __restrict__ Wtl,
    const float* __restrict__ bias, float* __restrict__ out,
    int F, int FO, int K5P, int relu)
{
    const int RW = 8 / CS;            // row-warps per block
    const int M = RW * 16;            // rows per block
    const int FOP = NT * 8 * CS;      // total padded output cols
    const int K5 = 5 * F;
    const int NCH = K5P >> 6;
    extern __shared__ char smem_raw[];
    uint32_t base = (smem_u32(smem_raw) + 1023u) & ~1023u;
    uint32_t AHI = base;
    uint32_t ALO = AHI + (uint32_t)(M * 128);
    uint32_t BHI = ALO + (uint32_t)(M * 128);
    uint32_t BLO = BHI + (uint32_t)(3 * FOP * 128);

    int tid = threadIdx.x;
    int wid = tid >> 5, lane = tid & 31;
    int warpRow = wid % RW, warpCol = wid / RW;
    int nbase = blockIdx.x * M;
    int r16 = lane & 15, c4 = lane >> 4;

    float acc[3][NT][4];
    #pragma unroll
    for (int j = 0; j < 3; j++)
        #pragma unroll
        for (int t = 0; t < NT; t++) {
            acc[j][t][0] = 0.f; acc[j][t][1] = 0.f;
            acc[j][t][2] = 0.f; acc[j][t][3] = 0.f;
        }

    for (int c = 0; c < NCH; c++) {
        int hasAgg = ((c + 1) * 64 > F);   // chunk touches agg columns?
        int nslab = hasAgg ? 3 : 1;
        __syncthreads();
        // ---- A' tile: M rows x 64 k, fp32 -> bf16 hi/lo (no scaling) ----
        for (int p = tid; p < M * 8; p += 256) {
            int row = p >> 3, g = p & 7;
            int n = nbase + row;
            int k = c * 64 + g * 8;
            float4 v0 = make_float4(0.f, 0.f, 0.f, 0.f), v1 = v0;
            if (n < N_NODES && k < K5) {
                const float* sp = (k < F) ? (h + (size_t)n * F + k)
                                          : (g_A + (size_t)n * 4 * F + (k - F));
                v0 = *(const float4*)sp;
                v1 = *(const float4*)(sp + 4);
            }
            float vv[8];
            vv[0] = v0.x; vv[1] = v0.y; vv[2] = v0.z; vv[3] = v0.w;
            vv[4] = v1.x; vv[5] = v1.y; vv[6] = v1.z; vv[7] = v1.w;
            uint32_t hi4[4], lo4[4];
            #pragma unroll
            for (int i = 0; i < 4; i++) {
                __nv_bfloat16 h0 = __float2bfloat16(vv[2 * i]);
                __nv_bfloat16 h1 = __float2bfloat16(vv[2 * i + 1]);
                float r0 = vv[2 * i] - __bfloat162float(h0);
                float r1 = vv[2 * i + 1] - __bfloat162float(h1);
                hi4[i] = pack2(h0, h1);
                lo4[i] = pack2(__float2bfloat16(r0), __float2bfloat16(r1));
            }
            uint32_t off = swz((uint32_t)(row * 128 + g * 16));
            sts128(AHI + off, hi4[0], hi4[1], hi4[2], hi4[3]);
            sts128(ALO + off, lo4[0], lo4[1], lo4[2], lo4[3]);
        }
        // ---- B tiles: nslab*FOP rows x 64 k from pre-split slabs ----
        for (int p = tid; p < nslab * FOP * 8; p += 256) {
            int row = p >> 3, g = p & 7;
            int k = c * 64 + g * 8;
            uint4 vh = *(const uint4*)(Wth + (size_t)row * K5P + k);
            uint4 vl = *(const uint4*)(Wtl + (size_t)row * K5P + k);
            uint32_t off = swz((uint32_t)(row * 128 + g * 16));
            sts128(BHI + off, vh.x, vh.y, vh.z, vh.w);
            sts128(BLO + off, vl.x, vl.y, vl.z, vl.w);
        }
        __syncthreads();
        // ---- compute: 4 k16-steps, shared A frags across the 3 slabs ----
        #pragma unroll
        for (int ks = 0; ks < 4; ks++) {
            uint32_t aoff = swz((uint32_t)((warpRow * 16 + r16) * 128 + ks * 32 + c4 * 16));
            uint32_t ah[4], al[4];
            ldsm4(ah, AHI + aoff);
            ldsm4(al, ALO + aoff);
            #pragma unroll
            for (int j = 0; j < 3; j++) {
                if (j > 0 && !hasAgg) continue;
                #pragma unroll
                for (int nt2 = 0; nt2 < NT / 2; nt2++) {
                    int brow = j * FOP + warpCol * NT * 8 + nt2 * 16;
                    uint32_t boff = swz((uint32_t)((brow + r16) * 128 + ks * 32 + c4 * 16));
                    uint32_t bh[4], bl[4];
                    ldsm4(bh, BHI + boff);
                    ldsm4(bl, BLO + boff);
                    int t0 = nt2 * 2, t1 = t0 + 1;
                    mma16816(acc[j][t0], ah, bh[0], bh[2]);
                    mma16816(acc[j][t0], ah, bl[0], bl[2]);
                    mma16816(acc[j][t0], al, bh[0], bh[2]);
                    mma16816(acc[j][t1], ah, bh[1], bh[3]);
                    mma16816(acc[j][t1], ah, bl[1], bl[3]);
                    mma16816(acc[j][t1], al, bh[1], bh[3]);
                }
            }
        }
    }
    // ---- epilogue: combine 3 acc sets with per-node scalers ----
    int n0 = nbase + warpRow * 16 + (lane >> 2);
    int n1 = n0 + 8;
    int cb = (lane & 3) * 2;
    float s1a = 0.f, s2a = 0.f, s1b = 0.f, s2b = 0.f;
    if (n0 < N_NODES) { s1a = g_s1[n0]; s2a = g_s2[n0]; }
    if (n1 < N_NODES) { s1b = g_s1[n1]; s2b = g_s2[n1]; }
    #pragma unroll
    for (int t = 0; t < NT; t++) {
        int col = warpCol * NT * 8 + t * 8 + cb;
        if (col < FO) {
            float b0 = bias[col];
            float b1 = (col + 1 < FO) ? bias[col + 1] : 0.f;
            if (n0 < N_NODES) {
                float u0 = acc[0][t][0] + s1a * acc[1][t][0] + s2a * acc[2][t][0] + b0;
                float u1 = acc[0][t][1] + s1a * acc[1][t][1] + s2a * acc[2][t][1] + b1;
                if (relu) { u0 = fmaxf(u0, 0.f); u1 = fmaxf(u1, 0.f); }
                out[(size_t)n0 * FO + col] = u0;
                if (col + 1 < FO) out[(size_t)n0 * FO + col + 1] = u1;
            }
            if (n1 < N_NODES) {
                float u2 = acc[0][t][2] + s1b * acc[1][t][2] + s2b * acc[2][t][2] + b0;
                float u3 = acc[0][t][3] + s1b * acc[1][t][3] + s2b * acc[2][t][3] + b1;
                if (relu) { u2 = fmaxf(u2, 0.f); u3 = fmaxf(u3, 0.f); }
                out[(size_t)n1 * FO + col] = u2;
                if (col + 1 < FO) out[(size_t)n1 * FO + col + 1] = u3;
            }
        }
    }
}

// ---------------- batch norm (deterministic 2-stage stats) ----------------
template <int C>
__global__ void k_bnstats(const float* __restrict__ Y) {
    __shared__ float shs[4][C];
    __shared__ float shss[4][C];
    int c = threadIdx.x, y = threadIdx.y;
    int n0 = blockIdx.x * 1024;
    int n1 = min(N_NODES, n0 + 1024);
    float s = 0.0f, ss = 0.0f;
    for (int n = n0 + y; n < n1; n += 4) {
        float v = Y[(size_t)n * C + c];
        s += v; ss += v * v;
    }
    shs[y][c] = s; shss[y][c] = ss;
    __syncthreads();
    if (y == 0) {
        float S  = shs[0][c] + shs[1][c] + shs[2][c] + shs[3][c];
        float SS = shss[0][c] + shss[1][c] + shss[2][c] + shss[3][c];
        g_part[blockIdx.x * 2 * C + c]     = S;
        g_part[blockIdx.x * 2 * C + C + c] = SS;
    }
}
template <int C>
__global__ void k_bnfin(const float* __restrict__ g, const float* __restrict__ be, int nb) {
    int c = threadIdx.x;
    if (c >= C) return;
    float s = 0.0f, ss = 0.0f;
    for (int i = 0; i < nb; i++) {
        s  += g_part[i * 2 * C + c];
        ss += g_part[i * 2 * C + C + c];
    }
    float mu = s / (float)N_NODES;
    float var = ss / (float)N_NODES - mu * mu;
    float sc = g[c] * rsqrtf(var + BN_EPS);
    g_scale[c] = sc;
    g_shift[c] = be[c] - mu * sc;
}
template <int C, bool RELU>
__global__ void k_bnapply(float* __restrict__ Y) {
    int i = blockIdx.x * blockDim.x + threadIdx.x;
    if (i < N_NODES * C) {
        int c = i % C;
        float v = fmaf(Y[i], g_scale[c], g_shift[c]);
        if (RELU) v = fmaxf(v, 0.0f);
        Y[i] = v;
    }
}

// ---------------- pooling + classifier head ----------------
__global__ void k_pool(const float* __restrict__ h, float* __restrict__ outz, int write_out) {
    int g = blockIdx.x;
    int c = threadIdx.x, y = threadIdx.y;
    int s = g_gstart[g], e = g_gstart[g + 1];
    float acc = 0.0f;
    if (c < 20)
        for (int n = s + y; n < e; n += 8) acc += h[(size_t)n * 20 + c];
    __shared__ float sh[8][32];
    sh[y][c] = acc;
    __syncthreads();
    if (y == 0 && c < 20) {
        float S = 0.0f;
        #pragma unroll
        for (int k = 0; k < 8; k++) S += sh[k][c];
        float cntf = fmaxf((float)(e - s), 1.0f);
        float z = S / cntf;
        g_z[g * 20 + c] = z;
        if (write_out) outz[g * 20 + c] = z;
    }
}
__global__ void k_final(const float* __restrict__ wlin, const float* __restrict__ blin,
                        float* __restrict__ out) {
    int g = blockIdx.x;
    int o = threadIdx.x;
    float l = -INFINITY;
    if (o < 11) {
        float s = blin[o];
        for (int k = 0; k < 20; k++) s = fmaf(g_z[g * 20 + k], wlin[k * 11 + o], s);
        l = s;
    }
    float m = l;
    #pragma unroll
    for (int off = 16; off; off >>= 1) m = fmaxf(m, __shfl_xor_sync(0xffffffffu, m, off));
    float ex = (o < 11) ? expf(l - m) : 0.0f;
    float sum = ex;
    #pragma unroll
    for (int off = 16; off; off >>= 1) sum += __shfl_xor_sync(0xffffffffu, sum, off);
    if (o < 11) out[g * 11 + o] = ex / sum;
}

// ---------------- host ----------------
extern "C" void kernel_launch(void* const* d_in, const int* in_sizes, int n_in,
                              void* d_out, int out_size) {
    const float* x     = (const float*)d_in[0];
    const int*   ei    = (const int*)d_in[1];
    const int*   batch = (const int*)d_in[2];
    const float* w0 = (const float*)d_in[3];  const float* b0 = (const float*)d_in[4];
    const float* w1 = (const float*)d_in[5];  const float* b1 = (const float*)d_in[6];
    const float* w2 = (const float*)d_in[7];  const float* b2 = (const float*)d_in[8];
    const float* w3 = (const float*)d_in[9];  const float* b3 = (const float*)d_in[10];
    const float* g0 = (const float*)d_in[11]; const float* be0 = (const float*)d_in[12];
    const float* g1 = (const float*)d_in[13]; const float* be1 = (const float*)d_in[14];
    const float* g2 = (const float*)d_in[15]; const float* be2 = (const float*)d_in[16];
    const float* wlin = (const float*)d_in[17]; const float* blin = (const float*)d_in[18];
    float* out = (float*)d_out;

    const int* src = ei;
    const int* dst = ei + N_EDGES;

    float *hA, *hB;
    __nv_bfloat16 *wth, *wtl;
    cudaGetSymbolAddress((void**)&hA, g_hA);
    cudaGetSymbolAddress((void**)&hB, g_hB);
    cudaGetSymbolAddress((void**)&wth, g_Wth);
    cudaGetSymbolAddress((void**)&wtl, g_Wtl);

    int nbE = (N_EDGES + 255) / 256;
    int nbN = (N_NODES + 255) / 256;

    // dynamic smem: 1024 pad + 2*M*128 (A hi/lo) + 2*3*FOP*128 (B hi/lo)
    const int SM_L0 = 1024 + 2 * 64 * 128 + 2 * 3 * 96 * 128;    // 91136  (<6,2>)
    const int SM_L1 = 1024 + 2 * 128 * 128 + 2 * 3 * 64 * 128;   // 82944  (<8,1>)
    const int SM_L23 = 1024 + 2 * 128 * 128 + 2 * 3 * 32 * 128;  // 58368  (<4,1>)
    typedef void (*gemm_fn)(const float*, const __nv_bfloat16*, const __nv_bfloat16*,
                            const float*, float*, int, int, int, int);
    gemm_fn f62 = k_mma_gemm<6, 2>;
    gemm_fn f81 = k_mma_gemm<8, 1>;
    gemm_fn f41 = k_mma_gemm<4, 1>;
    cudaFuncSetAttribute((const void*)f62, cudaFuncAttributeMaxDynamicSharedMemorySize, SM_L0);
    cudaFuncSetAttribute((const void*)f81, cudaFuncAttributeMaxDynamicSharedMemorySize, SM_L1);
    cudaFuncSetAttribute((const void*)f41, cudaFuncAttributeMaxDynamicSharedMemorySize, SM_L23);

    // CSR + per-node scalers (unsorted adjacency: fp reorder noise << 1e-3 tol)
    k_zero<<<nbN, 256>>>();
    k_hist<<<nbE, 256>>>(dst);
    k_scan<<<1, 1024>>>();
    k_scatter<<<nbE, 256>>>(src, dst);
    k_s1s2<<<nbN, 256>>>();
    k_bounds<<<nbN, 256>>>(batch);

    const int NBST = (N_NODES + 1023) / 1024;
    const int GB64  = (N_NODES + 63) / 64;     // 1563 (M=64 blocks)
    const int GB128 = (N_NODES + 127) / 128;   // 782

    // K5P = 5F padded to 64
    const int K5P0 = 320;   // F=64
    const int K5P1 = 512;   // F=96 (480 -> 512)
    const int K5P3 = 192;   // F=32 (160 -> 192)

    // Layer 0: 64 -> 96, BN + relu
    k_wsplit<<<(3 * 96 * K5P0 + 255) / 256, 256>>>(w0, 64, 96, 96, K5P0);
    k_agg<64><<<N_NODES, 64>>>(x);
    k_mma_gemm<6, 2><<<GB64, 256, SM_L0>>>(x, wth, wtl, b0, hA, 64, 96, K5P0, 0);
    k_bnstats<96><<<NBST, dim3(96, 4)>>>(hA);
    k_bnfin<96><<<1, 96>>>(g0, be0, NBST);
    k_bnapply<96, true><<<(N_NODES * 96 + 255) / 256, 256>>>(hA);

    // Layer 1: 96 -> 64, BN + relu
    k_wsplit<<<(3 * 64 * K5P1 + 255) / 256, 256>>>(w1, 96, 64, 64, K5P1);
    k_agg<96><<<N_NODES, 96>>>(hA);
    k_mma_gemm<8, 1><<<GB128, 256, SM_L1>>>(hA, wth, wtl, b1, hB, 96, 64, K5P1, 0);
    k_bnstats<64><<<NBST, dim3(64, 4)>>>(hB);
    k_bnfin<64><<<1, 64>>>(g1, be1, NBST);
    k_bnapply<64, true><<<(N_NODES * 64 + 255) / 256, 256>>>(hB);

    // Layer 2: 64 -> 32, relu (fused in epilogue)
    k_wsplit<<<(3 * 32 * K5P0 + 255) / 256, 256>>>(w2, 64, 32, 32, K5P0);
    k_agg<64><<<N_NODES, 64>>>(hB);
    k_mma_gemm<4, 1><<<GB128, 256, SM_L23>>>(hB, wth, wtl, b2, hA, 64, 32, K5P0, 1);

    // Layer 3: 32 -> 20, BN (no relu)
    k_wsplit<<<(3 * 32 * K5P3 + 255) / 256, 256>>>(w3, 32, 20, 32, K5P3);
    k_agg<32><<<N_NODES, 32>>>(hA);
    k_mma_gemm<4, 1><<<GB128, 256, SM_L23>>>(hA, wth, wtl, b3, hB, 32, 20, K5P3, 0);
    k_bnstats<20><<<NBST, dim3(20, 4)>>>(hB);
    k_bnfin<20><<<1, 20>>>(g2, be2, NBST);
    k_bnapply<20, false><<<(N_NODES * 20 + 255) / 256, 256>>>(hB);

    // Pool + head. Output layout: [softmax out (64x11) | z (64x20)]
    int write_z = (out_size >= 64 * 11 + 64 * 20) ? 1 : 0;
    k_pool<<<N_GRAPH, dim3(32, 8)>>>(hB, out + 64 * 11, write_z);
    k_final<<<N_GRAPH, 32>>>(wlin, blin, out);
}

// round 13
// speedup vs baseline: 1.8358x; 1.0564x over previous
#include <cuda_runtime.h>
#include <cuda_bf16.h>
#include <stdint.h>
#include <math.h>

#define N_NODES 100000
#define N_EDGES 3200000
#define N_GRAPH 64
#define AVG_LOG 3.4965075614664802f
#define BN_EPS 1e-5f
#define STD_EPS 1e-5f

// ---------------- scratch (device globals; no allocation allowed) ----------------
__device__ int   g_deg[N_NODES];
__device__ int   g_rowp[N_NODES + 1];
__device__ int   g_cur[N_NODES];
__device__ int   g_csr[N_EDGES];
__device__ float g_s1[N_NODES];
__device__ float g_s2[N_NODES];
__device__ float g_A[(size_t)N_NODES * 384];   // agg: [mean|min|max|std], F<=96
__device__ float g_hA[(size_t)N_NODES * 96];
__device__ float g_hB[(size_t)N_NODES * 96];
__device__ float g_part[128 * 192];            // BN partial sums
__device__ float g_scale[96];
__device__ float g_shift[96];
__device__ int   g_gstart[N_GRAPH + 1];
__device__ float g_z[N_GRAPH * 20];
__device__ __nv_bfloat16 g_Wth[3 * 96 * 512];  // weight bf16-hi, [3*FOP][K5P]
__device__ __nv_bfloat16 g_Wtl[3 * 96 * 512];  // weight bf16-lo

// ---------------- helpers (base-ISA only: ldmatrix + mma.sync) ----------------
__device__ __forceinline__ uint32_t smem_u32(const void* p) {
    uint32_t a;
    asm("{ .reg .u64 t; cvta.to.shared.u64 t, %1; cvt.u32.u64 %0, t; }" : "=r"(a) : "l"(p));
    return a;
}
__device__ __forceinline__ void ldsm4(uint32_t* r, uint32_t addr) {
    asm volatile("ldmatrix.sync.aligned.m8n8.x4.shared.b16 {%0,%1,%2,%3}, [%4];"
        : "=r"(r[0]), "=r"(r[1]), "=r"(r[2]), "=r"(r[3]) : "r"(addr));
}
__device__ __forceinline__ void mma16816(float* d, const uint32_t* a, uint32_t b0, uint32_t b1) {
    asm volatile(
        "mma.sync.aligned.m16n8k16.row.col.f32.bf16.bf16.f32 "
        "{%0,%1,%2,%3}, {%4,%5,%6,%7}, {%8,%9}, {%0,%1,%2,%3};"
        : "+f"(d[0]), "+f"(d[1]), "+f"(d[2]), "+f"(d[3])
        : "r"(a[0]), "r"(a[1]), "r"(a[2]), "r"(a[3]), "r"(b0), "r"(b1));
}
__device__ __forceinline__ void sts128(uint32_t a, uint32_t x, uint32_t y, uint32_t z, uint32_t w) {
    asm volatile("st.shared.v4.b32 [%0], {%1,%2,%3,%4};" :: "r"(a), "r"(x), "r"(y), "r"(z), "r"(w) : "memory");
}
__device__ __forceinline__ uint32_t swz(uint32_t off) { return off ^ ((off >> 3) & 0x70); }
__device__ __forceinline__ uint32_t pack2(__nv_bfloat16 a, __nv_bfloat16 b) {
    return (uint32_t)__bfloat16_as_ushort(a) | ((uint32_t)__bfloat16_as_ushort(b) << 16);
}

// ---------------- CSR build ----------------
__global__ void k_zero() {
    int i = blockIdx.x * blockDim.x + threadIdx.x;
    if (i < N_NODES) { g_deg[i] = 0; g_cur[i] = 0; }
}
__global__ void k_hist(const int* __restrict__ dst) {
    int e = blockIdx.x * blockDim.x + threadIdx.x;
    if (e < N_EDGES) atomicAdd(&g_deg[dst[e]], 1);
}
__global__ void k_scan() {
    __shared__ int warpsum[32];
    __shared__ int s_carry;
    int tid = threadIdx.x;
    int lane = tid & 31, wid = tid >> 5;
    if (tid == 0) s_carry = 0;
    __syncthreads();
    for (int base = 0; base < N_NODES; base += 1024) {
        int i = base + tid;
        int v = (i < N_NODES) ? g_deg[i] : 0;
        int x = v;
        #pragma unroll
        for (int off = 1; off < 32; off <<= 1) {
            int y = __shfl_up_sync(0xffffffffu, x, off);
            if (lane >= off) x += y;
        }
        if (lane == 31) warpsum[wid] = x;
        __syncthreads();
        if (wid == 0) {
            int w = warpsum[lane];
            #pragma unroll
            for (int off = 1; off < 32; off <<= 1) {
                int y = __shfl_up_sync(0xffffffffu, w, off);
                if (lane >= off) w += y;
            }
            warpsum[lane] = w;
        }
        __syncthreads();
        int excl = x - v + (wid > 0 ? warpsum[wid - 1] : 0);
        if (i < N_NODES) g_rowp[i] = s_carry + excl;
        __syncthreads();
        if (tid == 0) s_carry += warpsum[31];
        __syncthreads();
    }
    if (threadIdx.x == 0) g_rowp[N_NODES] = s_carry;
}
__global__ void k_scatter(const int* __restrict__ src, const int* __restrict__ dst) {
    int e = blockIdx.x * blockDim.x + threadIdx.x;
    if (e < N_EDGES) {
        int d = dst[e];
        int pos = atomicAdd(&g_cur[d], 1);
        g_csr[g_rowp[d] + pos] = src[e];
    }
}
// merged per-node scalers + graph boundaries (one launch)
__global__ void k_s1s2b(const int* __restrict__ batch) {
    int i = blockIdx.x * blockDim.x + threadIdx.x;
    if (i >= N_NODES) return;
    float degc = fmaxf((float)g_deg[i], 1.0f);
    float logd = logf(degc + 1.0f);
    g_s1[i] = logd / AVG_LOG;
    g_s2[i] = AVG_LOG / logd;
    if (i == 0) {
        for (int g = 0; g <= batch[0]; g++) g_gstart[g] = 0;
    } else {
        int b0 = batch[i - 1], b1 = batch[i];
        if (b1 != b0) for (int g = b0 + 1; g <= b1; g++) g_gstart[g] = i;
    }
    if (i == N_NODES - 1) {
        for (int g = batch[i] + 1; g <= N_GRAPH; g++) g_gstart[g] = N_NODES;
    }
}

// ---------------- aggregation: warp-per-node, shfl index broadcast ----------------
// One warp per node; indices fetched 32-at-a-time (coalesced) then broadcast via shfl.
// No smem, no block syncs. Accumulation order over neighbors identical to CSR order.
template <int F>
__global__ void __launch_bounds__(256) k_agg(const float* __restrict__ h) {
    int gw = (blockIdx.x * 256 + threadIdx.x) >> 5;   // warp-uniform
    if (gw >= N_NODES) return;
    int lane = threadIdx.x & 31;
    int s = g_rowp[gw], e = g_rowp[gw + 1];
    int deg = e - s;

    float sm0 = 0.f, sm1 = 0.f, sm2 = 0.f;
    float ss0 = 0.f, ss1 = 0.f, ss2 = 0.f;
    float mn0 = INFINITY, mn1 = INFINITY, mn2 = INFINITY;
    float mx0 = -INFINITY, mx1 = -INFINITY, mx2 = -INFINITY;

    for (int c0 = s; c0 < e; c0 += 32) {
        int m = e - c0; if (m > 32) m = 32;
        int nb = (lane < m) ? g_csr[c0 + lane] : 0;
        for (int j = 0; j < m; j++) {
            int idx = __shfl_sync(0xffffffffu, nb, j);
            const float* row = h + (size_t)idx * F;
            if (F >= 64) {
                float2 v = *(const float2*)(row + 2 * lane);
                sm0 += v.x; ss0 = fmaf(v.x, v.x, ss0);
                mn0 = fminf(mn0, v.x); mx0 = fmaxf(mx0, v.x);
                sm1 += v.y; ss1 = fmaf(v.y, v.y, ss1);
                mn1 = fminf(mn1, v.y); mx1 = fmaxf(mx1, v.y);
            }
            if (F == 96) {
                float v = row[64 + lane];
                sm2 += v; ss2 = fmaf(v, v, ss2);
                mn2 = fminf(mn2, v); mx2 = fmaxf(mx2, v);
            }
            if (F == 32) {
                float v = row[lane];
                sm0 += v; ss0 = fmaf(v, v, ss0);
                mn0 = fminf(mn0, v); mx0 = fmaxf(mx0, v);
            }
        }
    }
    float degc = fmaxf((float)deg, 1.0f);
    float inv = 1.0f / degc;
    if (deg == 0) {
        mn0 = 0.f; mx0 = 0.f; mn1 = 0.f; mx1 = 0.f; mn2 = 0.f; mx2 = 0.f;
    }
    float* base = g_A + (size_t)gw * (4 * F);
    if (F >= 64) {
        float mean0 = sm0 * inv, mean1 = sm1 * inv;
        float sd0 = sqrtf(fmaxf(ss0 * inv - mean0 * mean0, 0.f) + STD_EPS);
        float sd1 = sqrtf(fmaxf(ss1 * inv - mean1 * mean1, 0.f) + STD_EPS);
        *(float2*)(base + 2 * lane)         = make_float2(mean0, mean1);
        *(float2*)(base + F + 2 * lane)     = make_float2(mn0, mn1);
        *(float2*)(base + 2 * F + 2 * lane) = make_float2(mx0, mx1);
        *(float2*)(base + 3 * F + 2 * lane) = make_float2(sd0, sd1);
    }
    if (F == 96) {
        float mean2 = sm2 * inv;
        float sd2 = sqrtf(fmaxf(ss2 * inv - mean2 * mean2, 0.f) + STD_EPS);
        base[64 + lane]         = mean2;
        base[F + 64 + lane]     = mn2;
        base[2 * F + 64 + lane] = mx2;
        base[3 * F + 64 + lane] = sd2;
    }
    if (F == 32) {
        float mean0 = sm0 * inv;
        float sd0 = sqrtf(fmaxf(ss0 * inv - mean0 * mean0, 0.f) + STD_EPS);
        base[lane]         = mean0;
        base[F + lane]     = mn0;
        base[2 * F + lane] = mx0;
        base[3 * F + lane] = sd0;
    }
}

// ---------------- weight pre-split: W[13F,FO] -> 3 slabs [3*FOP][K5P] bf16 hi/lo ----
__global__ void k_wsplit(const float* __restrict__ W, int F, int FO, int FOP, int K5P) {
    int K5 = 5 * F;
    int total = 3 * FOP * K5P;
    int idx = blockIdx.x * blockDim.x + threadIdx.x;
    if (idx >= total) return;
    int row = idx / K5P, k = idx - row * K5P;
    int j = row / FOP, o = row - j * FOP;
    float v = 0.0f;
    if (o < FO && k < K5) {
        if (j == 0) v = W[(size_t)k * FO + o];
        else if (k >= F) v = W[(size_t)(4 * F * j + k) * FO + o];
    }
    __nv_bfloat16 hi = __float2bfloat16(v);
    float r = v - __bfloat162float(hi);
    g_Wth[idx] = hi;
    g_Wtl[idx] = __float2bfloat16(r);
}

// ---------------- mma.sync fused PNA GEMM (3 accumulator sets) ----------------
template <int NT, int CS>
__global__ __launch_bounds__(256) void k_mma_gemm(
    const float* __restrict__ h,
    const __nv_bfloat16* __restrict__ Wth, const __nv_bfloat16* __restrict__ Wtl,
    const float* __restrict__ bias, float* __restrict__ out,
    int F, int FO, int K5P, int relu)
{
    const int RW = 8 / CS;
    const int M = RW * 16;
    const int FOP = NT * 8 * CS;
    const int K5 = 5 * F;
    const int NCH = K5P >> 6;
    extern __shared__ char smem_raw[];
    uint32_t base = (smem_u32(smem_raw) + 1023u) & ~1023u;
    uint32_t AHI = base;
    uint32_t ALO = AHI + (uint32_t)(M * 128);
    uint32_t BHI = ALO + (uint32_t)(M * 128);
    uint32_t BLO = BHI + (uint32_t)(3 * FOP * 128);

    int tid = threadIdx.x;
    int wid = tid >> 5, lane = tid & 31;
    int warpRow = wid % RW, warpCol = wid / RW;
    int nbase = blockIdx.x * M;
    int r16 = lane & 15, c4 = lane >> 4;

    float acc[3][NT][4];
    #pragma unroll
    for (int j = 0; j < 3; j++)
        #pragma unroll
        for (int t = 0; t < NT; t++) {
            acc[j][t][0] = 0.f; acc[j][t][1] = 0.f;
            acc[j][t][2] = 0.f; acc[j][t][3] = 0.f;
        }

    for (int c = 0; c < NCH; c++) {
        int hasAgg = ((c + 1) * 64 > F);
        int nslab = hasAgg ? 3 : 1;
        __syncthreads();
        for (int p = tid; p < M * 8; p += 256) {
            int row = p >> 3, g = p & 7;
            int n = nbase + row;
            int k = c * 64 + g * 8;
            float4 v0 = make_float4(0.f, 0.f, 0.f, 0.f), v1 = v0;
            if (n < N_NODES && k < K5) {
                const float* sp = (k < F) ? (h + (size_t)n * F + k)
                                          : (g_A + (size_t)n * 4 * F + (k - F));
                v0 = *(const float4*)sp;
                v1 = *(const float4*)(sp + 4);
            }
            float vv[8];
            vv[0] = v0.x; vv[1] = v0.y; vv[2] = v0.z; vv[3] = v0.w;
            vv[4] = v1.x; vv[5] = v1.y; vv[6] = v1.z; vv[7] = v1.w;
            uint32_t hi4[4], lo4[4];
            #pragma unroll
            for (int i = 0; i < 4; i++) {
                __nv_bfloat16 h0 = __float2bfloat16(vv[2 * i]);
                __nv_bfloat16 h1 = __float2bfloat16(vv[2 * i + 1]);
                float r0 = vv[2 * i] - __bfloat162float(h0);
                float r1 = vv[2 * i + 1] - __bfloat162float(h1);
                hi4[i] = pack2(h0, h1);
                lo4[i] = pack2(__float2bfloat16(r0), __float2bfloat16(r1));
            }
            uint32_t off = swz((uint32_t)(row * 128 + g * 16));
            sts128(AHI + off, hi4[0], hi4[1], hi4[2], hi4[3]);
            sts128(ALO + off, lo4[0], lo4[1], lo4[2], lo4[3]);
        }
        for (int p = tid; p < nslab * FOP * 8; p += 256) {
            int row = p >> 3, g = p & 7;
            int k = c * 64 + g * 8;
            uint4 vh = *(const uint4*)(Wth + (size_t)row * K5P + k);
            uint4 vl = *(const uint4*)(Wtl + (size_t)row * K5P + k);
            uint32_t off = swz((uint32_t)(row * 128 + g * 16));
            sts128(BHI + off, vh.x, vh.y, vh.z, vh.w);
            sts128(BLO + off, vl.x, vl.y, vl.z, vl.w);
        }
        __syncthreads();
        #pragma unroll
        for (int ks = 0; ks < 4; ks++) {
            uint32_t aoff = swz((uint32_t)((warpRow * 16 + r16) * 128 + ks * 32 + c4 * 16));
            uint32_t ah[4], al[4];
            ldsm4(ah, AHI + aoff);
            ldsm4(al, ALO + aoff);
            #pragma unroll
            for (int j = 0; j < 3; j++) {
                if (j > 0 && !hasAgg) continue;
                #pragma unroll
                for (int nt2 = 0; nt2 < NT / 2; nt2++) {
                    int brow = j * FOP + warpCol * NT * 8 + nt2 * 16;
                    uint32_t boff = swz((uint32_t)((brow + r16) * 128 + ks * 32 + c4 * 16));
                    uint32_t bh[4], bl[4];
                    ldsm4(bh, BHI + boff);
                    ldsm4(bl, BLO + boff);
                    int t0 = nt2 * 2, t1 = t0 + 1;
                    mma16816(acc[j][t0], ah, bh[0], bh[2]);
                    mma16816(acc[j][t0], ah, bl[0], bl[2]);
                    mma16816(acc[j][t0], al, bh[0], bh[2]);
                    mma16816(acc[j][t1], ah, bh[1], bh[3]);
                    mma16816(acc[j][t1], ah, bl[1], bl[3]);
                    mma16816(acc[j][t1], al, bh[1], bh[3]);
                }
            }
        }
    }
    int n0 = nbase + warpRow * 16 + (lane >> 2);
    int n1 = n0 + 8;
    int cb = (lane & 3) * 2;
    float s1a = 0.f, s2a = 0.f, s1b = 0.f, s2b = 0.f;
    if (n0 < N_NODES) { s1a = g_s1[n0]; s2a = g_s2[n0]; }
    if (n1 < N_NODES) { s1b = g_s1[n1]; s2b = g_s2[n1]; }
    #pragma unroll
    for (int t = 0; t < NT; t++) {
        int col = warpCol * NT * 8 + t * 8 + cb;
        if (col < FO) {
            float b0 = bias[col];
            float b1 = (col + 1 < FO) ? bias[col + 1] : 0.f;
            if (n0 < N_NODES) {
                float u0 = acc[0][t][0] + s1a * acc[1][t][0] + s2a * acc[2][t][0] + b0;
                float u1 = acc[0][t][1] + s1a * acc[1][t][1] + s2a * acc[2][t][1] + b1;
                if (relu) { u0 = fmaxf(u0, 0.f); u1 = fmaxf(u1, 0.f); }
                out[(size_t)n0 * FO + col] = u0;
                if (col + 1 < FO) out[(size_t)n0 * FO + col + 1] = u1;
            }
            if (n1 < N_NODES) {
                float u2 = acc[0][t][2] + s1b * acc[1][t][2] + s2b * acc[2][t][2] + b0;
                float u3 = acc[0][t][3] + s1b * acc[1][t][3] + s2b * acc[2][t][3] + b1;
                if (relu) { u2 = fmaxf(u2, 0.f); u3 = fmaxf(u3, 0.f); }
                out[(size_t)n1 * FO + col] = u2;
                if (col + 1 < FO) out[(size_t)n1 * FO + col + 1] = u3;
            }
        }
    }
}

// ---------------- batch norm (deterministic 2-stage stats) ----------------
template <int C>
__global__ void k_bnstats(const float* __restrict__ Y) {
    __shared__ float shs[4][C];
    __shared__ float shss[4][C];
    int c = threadIdx.x, y = threadIdx.y;
    int n0 = blockIdx.x * 1024;
    int n1 = min(N_NODES, n0 + 1024);
    float s = 0.0f, ss = 0.0f;
    for (int n = n0 + y; n < n1; n += 4) {
        float v = Y[(size_t)n * C + c];
        s += v; ss += v * v;
    }
    shs[y][c] = s; shss[y][c] = ss;
    __syncthreads();
    if (y == 0) {
        float S  = shs[0][c] + shs[1][c] + shs[2][c] + shs[3][c];
        float SS = shss[0][c] + shss[1][c] + shss[2][c] + shss[3][c];
        g_part[blockIdx.x * 2 * C + c]     = S;
        g_part[blockIdx.x * 2 * C + C + c] = SS;
    }
}
template <int C>
__global__ void k_bnfin(const float* __restrict__ g, const float* __restrict__ be, int nb) {
    int c = threadIdx.x;
    if (c >= C) return;
    float s = 0.0f, ss = 0.0f;
    for (int i = 0; i < nb; i++) {
        s  += g_part[i * 2 * C + c];
        ss += g_part[i * 2 * C + C + c];
    }
    float mu = s / (float)N_NODES;
    float var = ss / (float)N_NODES - mu * mu;
    float sc = g[c] * rsqrtf(var + BN_EPS);
    g_scale[c] = sc;
    g_shift[c] = be[c] - mu * sc;
}
template <int C, bool RELU>
__global__ void k_bnapply(float* __restrict__ Y) {
    int i = blockIdx.x * blockDim.x + threadIdx.x;
    if (i < N_NODES * C) {
        int c = i % C;
        float v = fmaf(Y[i], g_scale[c], g_shift[c]);
        if (RELU) v = fmaxf(v, 0.0f);
        Y[i] = v;
    }
}

// ---------------- pooling + classifier head ----------------
__global__ void k_pool(const float* __restrict__ h, float* __restrict__ outz, int write_out) {
    int g = blockIdx.x;
    int c = threadIdx.x, y = threadIdx.y;
    int s = g_gstart[g], e = g_gstart[g + 1];
    float acc = 0.0f;
    if (c < 20)
        for (int n = s + y; n < e; n += 8) acc += h[(size_t)n * 20 + c];
    __shared__ float sh[8][32];
    sh[y][c] = acc;
    __syncthreads();
    if (y == 0 && c < 20) {
        float S = 0.0f;
        #pragma unroll
        for (int k = 0; k < 8; k++) S += sh[k][c];
        float cntf = fmaxf((float)(e - s), 1.0f);
        float z = S / cntf;
        g_z[g * 20 + c] = z;
        if (write_out) outz[g * 20 + c] = z;
    }
}
__global__ void k_final(const float* __restrict__ wlin, const float* __restrict__ blin,
                        float* __restrict__ out) {
    int g = blockIdx.x;
    int o = threadIdx.x;
    float l = -INFINITY;
    if (o < 11) {
        float s = blin[o];
        for (int k = 0; k < 20; k++) s = fmaf(g_z[g * 20 + k], wlin[k * 11 + o], s);
        l = s;
    }
    float m = l;
    #pragma unroll
    for (int off = 16; off; off >>= 1) m = fmaxf(m, __shfl_xor_sync(0xffffffffu, m, off));
    float ex = (o < 11) ? expf(l - m) : 0.0f;
    float sum = ex;
    #pragma unroll
    for (int off = 16; off; off >>= 1) sum += __shfl_xor_sync(0xffffffffu, sum, off);
    if (o < 11) out[g * 11 + o] = ex / sum;
}

// ---------------- host ----------------
extern "C" void kernel_launch(void* const* d_in, const int* in_sizes, int n_in,
                              void* d_out, int out_size) {
    const float* x     = (const float*)d_in[0];
    const int*   ei    = (const int*)d_in[1];
    const int*   batch = (const int*)d_in[2];
    const float* w0 = (const float*)d_in[3];  const float* b0 = (const float*)d_in[4];
    const float* w1 = (const float*)d_in[5];  const float* b1 = (const float*)d_in[6];
    const float* w2 = (const float*)d_in[7];  const float* b2 = (const float*)d_in[8];
    const float* w3 = (const float*)d_in[9];  const float* b3 = (const float*)d_in[10];
    const float* g0 = (const float*)d_in[11]; const float* be0 = (const float*)d_in[12];
    const float* g1 = (const float*)d_in[13]; const float* be1 = (const float*)d_in[14];
    const float* g2 = (const float*)d_in[15]; const float* be2 = (const float*)d_in[16];
    const float* wlin = (const float*)d_in[17]; const float* blin = (const float*)d_in[18];
    float* out = (float*)d_out;

    const int* src = ei;
    const int* dst = ei + N_EDGES;

    float *hA, *hB;
    __nv_bfloat16 *wth, *wtl;
    cudaGetSymbolAddress((void**)&hA, g_hA);
    cudaGetSymbolAddress((void**)&hB, g_hB);
    cudaGetSymbolAddress((void**)&wth, g_Wth);
    cudaGetSymbolAddress((void**)&wtl, g_Wtl);

    int nbE = (N_EDGES + 255) / 256;
    int nbN = (N_NODES + 255) / 256;

    const int SM_L0 = 1024 + 2 * 64 * 128 + 2 * 3 * 96 * 128;    // 91136  (<6,2>)
    const int SM_L1 = 1024 + 2 * 128 * 128 + 2 * 3 * 64 * 128;   // 82944  (<8,1>)
    const int SM_L23 = 1024 + 2 * 128 * 128 + 2 * 3 * 32 * 128;  // 58368  (<4,1>)
    typedef void (*gemm_fn)(const float*, const __nv_bfloat16*, const __nv_bfloat16*,
                            const float*, float*, int, int, int, int);
    gemm_fn f62 = k_mma_gemm<6, 2>;
    gemm_fn f81 = k_mma_gemm<8, 1>;
    gemm_fn f41 = k_mma_gemm<4, 1>;
    cudaFuncSetAttribute((const void*)f62, cudaFuncAttributeMaxDynamicSharedMemorySize, SM_L0);
    cudaFuncSetAttribute((const void*)f81, cudaFuncAttributeMaxDynamicSharedMemorySize, SM_L1);
    cudaFuncSetAttribute((const void*)f41, cudaFuncAttributeMaxDynamicSharedMemorySize, SM_L23);

    // CSR + per-node scalers
    k_zero<<<nbN, 256>>>();
    k_hist<<<nbE, 256>>>(dst);
    k_scan<<<1, 1024>>>();
    k_scatter<<<nbE, 256>>>(src, dst);
    k_s1s2b<<<nbN, 256>>>(batch);

    const int NBST = (N_NODES + 1023) / 1024;
    const int GB64  = (N_NODES + 63) / 64;
    const int GB128 = (N_NODES + 127) / 128;
    const int AGGB  = (N_NODES * 32 + 255) / 256;   // warp-per-node agg blocks

    const int K5P0 = 320;   // F=64
    const int K5P1 = 512;   // F=96
    const int K5P3 = 192;   // F=32

    // Layer 0: 64 -> 96, BN + relu
    k_wsplit<<<(3 * 96 * K5P0 + 255) / 256, 256>>>(w0, 64, 96, 96, K5P0);
    k_agg<64><<<AGGB, 256>>>(x);
    k_mma_gemm<6, 2><<<GB64, 256, SM_L0>>>(x, wth, wtl, b0, hA, 64, 96, K5P0, 0);
    k_bnstats<96><<<NBST, dim3(96, 4)>>>(hA);
    k_bnfin<96><<<1, 96>>>(g0, be0, NBST);
    k_bnapply<96, true><<<(N_NODES * 96 + 255) / 256, 256>>>(hA);

    // Layer 1: 96 -> 64, BN + relu
    k_wsplit<<<(3 * 64 * K5P1 + 255) / 256, 256>>>(w1, 96, 64, 64, K5P1);
    k_agg<96><<<AGGB, 256>>>(hA);
    k_mma_gemm<8, 1><<<GB128, 256, SM_L1>>>(hA, wth, wtl, b1, hB, 96, 64, K5P1, 0);
    k_bnstats<64><<<NBST, dim3(64, 4)>>>(hB);
    k_bnfin<64><<<1, 64>>>(g1, be1, NBST);
    k_bnapply<64, true><<<(N_NODES * 64 + 255) / 256, 256>>>(hB);

    // Layer 2: 64 -> 32, relu (fused in epilogue)
    k_wsplit<<<(3 * 32 * K5P0 + 255) / 256, 256>>>(w2, 64, 32, 32, K5P0);
    k_agg<64><<<AGGB, 256>>>(hB);
    k_mma_gemm<4, 1><<<GB128, 256, SM_L23>>>(hB, wth, wtl, b2, hA, 64, 32, K5P0, 1);

    // Layer 3: 32 -> 20, BN (no relu)
    k_wsplit<<<(3 * 32 * K5P3 + 255) / 256, 256>>>(w3, 32, 20, 32, K5P3);
    k_agg<32><<<AGGB, 256>>>(hA);
    k_mma_gemm<4, 1><<<GB128, 256, SM_L23>>>(hA, wth, wtl, b3, hB, 32, 20, K5P3, 0);
    k_bnstats<20><<<NBST, dim3(20, 4)>>>(hB);
    k_bnfin<20><<<1, 20>>>(g2, be2, NBST);
    k_bnapply<20, false><<<(N_NODES * 20 + 255) / 256, 256>>>(hB);

    // Pool + head. Output layout: [softmax out (64x11) | z (64x20)]
    int write_z = (out_size >= 64 * 11 + 64 * 20) ? 1 : 0;
    k_pool<<<N_GRAPH, dim3(32, 8)>>>(hB, out + 64 * 11, write_z);
    k_final<<<N_GRAPH, 32>>>(wlin, blin, out);
}

// round 14
// speedup vs baseline: 2.1137x; 1.1514x over previous
#include <cuda_runtime.h>
#include <cuda_bf16.h>
#include <stdint.h>
#include <math.h>

#define N_NODES 100000
#define N_EDGES 3200000
#define N_GRAPH 64
#define AVG_LOG 3.4965075614664802f
#define BN_EPS 1e-5f
#define STD_EPS 1e-5f
#define NB_SCAN 98    // ceil(N_NODES/1024)

// ---------------- scratch (device globals; no allocation allowed) ----------------
__device__ int   g_deg[N_NODES];
__device__ int   g_rowp[N_NODES + 1];
__device__ int   g_cur[N_NODES];
__device__ int   g_csr[N_EDGES];
__device__ int   g_bsum[NB_SCAN];
__device__ float g_s1[N_NODES];
__device__ float g_s2[N_NODES];
__device__ float g_hA[(size_t)N_NODES * 96];
__device__ float g_hB[(size_t)N_NODES * 96];
__device__ float g_part[128 * 192];            // BN partial sums
__device__ float g_scale[96];
__device__ float g_shift[96];
__device__ int   g_gstart[N_GRAPH + 1];
__device__ float g_z[N_GRAPH * 20];
__device__ __nv_bfloat16 g_Wth[3 * 96 * 512];  // weight bf16-hi, [3*FOP][K5P]
__device__ __nv_bfloat16 g_Wtl[3 * 96 * 512];  // weight bf16-lo
// bf16 hi/lo activation + agg buffers (uint4-typed for 16B alignment)
__device__ uint4 g_Ah_[(size_t)N_NODES * 48];  // agg hi: N x 4F (F<=96) bf16
__device__ uint4 g_Al_[(size_t)N_NODES * 48];  // agg lo
__device__ uint4 g_Xh0_[(size_t)N_NODES * 12]; // act hi set0: N x 96 bf16
__device__ uint4 g_Xl0_[(size_t)N_NODES * 12];
__device__ uint4 g_Xh1_[(size_t)N_NODES * 12]; // act hi set1
__device__ uint4 g_Xl1_[(size_t)N_NODES * 12];

// ---------------- helpers (base-ISA only: ldmatrix + mma.sync) ----------------
__device__ __forceinline__ uint32_t smem_u32(const void* p) {
    uint32_t a;
    asm("{ .reg .u64 t; cvta.to.shared.u64 t, %1; cvt.u32.u64 %0, t; }" : "=r"(a) : "l"(p));
    return a;
}
__device__ __forceinline__ void ldsm4(uint32_t* r, uint32_t addr) {
    asm volatile("ldmatrix.sync.aligned.m8n8.x4.shared.b16 {%0,%1,%2,%3}, [%4];"
        : "=r"(r[0]), "=r"(r[1]), "=r"(r[2]), "=r"(r[3]) : "r"(addr));
}
__device__ __forceinline__ void mma16816(float* d, const uint32_t* a, uint32_t b0, uint32_t b1) {
    asm volatile(
        "mma.sync.aligned.m16n8k16.row.col.f32.bf16.bf16.f32 "
        "{%0,%1,%2,%3}, {%4,%5,%6,%7}, {%8,%9}, {%0,%1,%2,%3};"
        : "+f"(d[0]), "+f"(d[1]), "+f"(d[2]), "+f"(d[3])
        : "r"(a[0]), "r"(a[1]), "r"(a[2]), "r"(a[3]), "r"(b0), "r"(b1));
}
__device__ __forceinline__ void sts128(uint32_t a, uint32_t x, uint32_t y, uint32_t z, uint32_t w) {
    asm volatile("st.shared.v4.b32 [%0], {%1,%2,%3,%4};" :: "r"(a), "r"(x), "r"(y), "r"(z), "r"(w) : "memory");
}
__device__ __forceinline__ uint32_t swz(uint32_t off) { return off ^ ((off >> 3) & 0x70); }
__device__ __forceinline__ uint32_t pack2(__nv_bfloat16 a, __nv_bfloat16 b) {
    return (uint32_t)__bfloat16_as_ushort(a) | ((uint32_t)__bfloat16_as_ushort(b) << 16);
}
// split two fp32 into packed bf16 hi + packed bf16 lo
__device__ __forceinline__ void split2(float v0, float v1, uint32_t& hi, uint32_t& lo) {
    __nv_bfloat16 h0 = __float2bfloat16(v0);
    __nv_bfloat16 h1 = __float2bfloat16(v1);
    hi = pack2(h0, h1);
    lo = pack2(__float2bfloat16(v0 - __bfloat162float(h0)),
               __float2bfloat16(v1 - __bfloat162float(h1)));
}

// ---------------- CSR build ----------------
__global__ void k_zero() {
    int i = blockIdx.x * blockDim.x + threadIdx.x;
    if (i < N_NODES) { g_deg[i] = 0; g_cur[i] = 0; }
}
__global__ void k_hist(const int* __restrict__ dst) {
    int e = blockIdx.x * blockDim.x + threadIdx.x;
    if (e < N_EDGES) atomicAdd(&g_deg[dst[e]], 1);
}
// multi-block scan: per-block local exclusive prefix + block totals
__global__ void k_scanA() {
    __shared__ int warpsum[32];
    int tid = threadIdx.x, lane = tid & 31, wid = tid >> 5;
    int i = blockIdx.x * 1024 + tid;
    int v = (i < N_NODES) ? g_deg[i] : 0;
    int x = v;
    #pragma unroll
    for (int off = 1; off < 32; off <<= 1) {
        int y = __shfl_up_sync(0xffffffffu, x, off);
        if (lane >= off) x += y;
    }
    if (lane == 31) warpsum[wid] = x;
    __syncthreads();
    if (wid == 0) {
        int w = warpsum[lane];
        #pragma unroll
        for (int off = 1; off < 32; off <<= 1) {
            int y = __shfl_up_sync(0xffffffffu, w, off);
            if (lane >= off) w += y;
        }
        warpsum[lane] = w;
    }
    __syncthreads();
    int excl = x - v + (wid > 0 ? warpsum[wid - 1] : 0);
    if (i < N_NODES) g_rowp[i] = excl;
    if (tid == 1023) g_bsum[blockIdx.x] = excl + v;
}
__global__ void k_scanB() {
    __shared__ int s_off;
    if (threadIdx.x == 0) {
        int o = 0;
        for (int b = 0; b < (int)blockIdx.x; b++) o += g_bsum[b];
        s_off = o;
    }
    __syncthreads();
    int i = blockIdx.x * 1024 + threadIdx.x;
    if (i < N_NODES) g_rowp[i] += s_off;
    if (i == 0) g_rowp[N_NODES] = N_EDGES;
}
__global__ void k_scatter(const int* __restrict__ src, const int* __restrict__ dst) {
    int e = blockIdx.x * blockDim.x + threadIdx.x;
    if (e < N_EDGES) {
        int d = dst[e];
        int pos = atomicAdd(&g_cur[d], 1);
        g_csr[g_rowp[d] + pos] = src[e];
    }
}
// merged per-node scalers + graph boundaries
__global__ void k_s1s2b(const int* __restrict__ batch) {
    int i = blockIdx.x * blockDim.x + threadIdx.x;
    if (i >= N_NODES) return;
    float degc = fmaxf((float)g_deg[i], 1.0f);
    float logd = logf(degc + 1.0f);
    g_s1[i] = logd / AVG_LOG;
    g_s2[i] = AVG_LOG / logd;
    if (i == 0) {
        for (int g = 0; g <= batch[0]; g++) g_gstart[g] = 0;
    } else {
        int b0 = batch[i - 1], b1 = batch[i];
        if (b1 != b0) for (int g = b0 + 1; g <= b1; g++) g_gstart[g] = i;
    }
    if (i == N_NODES - 1) {
        for (int g = batch[i] + 1; g <= N_GRAPH; g++) g_gstart[g] = N_NODES;
    }
}

// ---------------- input convert: x fp32 -> bf16 hi/lo ----------------
__global__ void k_convx(const float* __restrict__ x, uint32_t* __restrict__ xh,
                        uint32_t* __restrict__ xl, int total2) {
    int i = blockIdx.x * blockDim.x + threadIdx.x;
    if (i < total2) {
        float2 v = *(const float2*)(x + 2 * i);
        uint32_t hi, lo;
        split2(v.x, v.y, hi, lo);
        xh[i] = hi; xl[i] = lo;
    }
}

// ---------------- aggregation: warp-per-node, writes bf16 hi/lo directly ----------------
template <int F>
__global__ void __launch_bounds__(256) k_agg(const float* __restrict__ h) {
    int gw = (blockIdx.x * 256 + threadIdx.x) >> 5;
    if (gw >= N_NODES) return;
    int lane = threadIdx.x & 31;
    int s = g_rowp[gw], e = g_rowp[gw + 1];
    int deg = e - s;

    float sm0 = 0.f, sm1 = 0.f, sm2 = 0.f;
    float ss0 = 0.f, ss1 = 0.f, ss2 = 0.f;
    float mn0 = INFINITY, mn1 = INFINITY, mn2 = INFINITY;
    float mx0 = -INFINITY, mx1 = -INFINITY, mx2 = -INFINITY;

    for (int c0 = s; c0 < e; c0 += 32) {
        int m = e - c0; if (m > 32) m = 32;
        int nb = (lane < m) ? g_csr[c0 + lane] : 0;
        for (int j = 0; j < m; j++) {
            int idx = __shfl_sync(0xffffffffu, nb, j);
            const float* row = h + (size_t)idx * F;
            if (F >= 64) {
                float2 v = *(const float2*)(row + 2 * lane);
                sm0 += v.x; ss0 = fmaf(v.x, v.x, ss0);
                mn0 = fminf(mn0, v.x); mx0 = fmaxf(mx0, v.x);
                sm1 += v.y; ss1 = fmaf(v.y, v.y, ss1);
                mn1 = fminf(mn1, v.y); mx1 = fmaxf(mx1, v.y);
            }
            if (F == 96) {
                float v = row[64 + lane];
                sm2 += v; ss2 = fmaf(v, v, ss2);
                mn2 = fminf(mn2, v); mx2 = fmaxf(mx2, v);
            }
            if (F == 32) {
                float v = row[lane];
                sm0 += v; ss0 = fmaf(v, v, ss0);
                mn0 = fminf(mn0, v); mx0 = fmaxf(mx0, v);
            }
        }
    }
    float degc = fmaxf((float)deg, 1.0f);
    float inv = 1.0f / degc;
    if (deg == 0) {
        mn0 = 0.f; mx0 = 0.f; mn1 = 0.f; mx1 = 0.f; mn2 = 0.f; mx2 = 0.f;
    }
    uint32_t* Ah = (uint32_t*)g_Ah_;
    uint32_t* Al = (uint32_t*)g_Al_;
    if (F >= 64) {
        float mean0 = sm0 * inv, mean1 = sm1 * inv;
        float sd0 = sqrtf(fmaxf(ss0 * inv - mean0 * mean0, 0.f) + STD_EPS);
        float sd1 = sqrtf(fmaxf(ss1 * inv - mean1 * mean1, 0.f) + STD_EPS);
        size_t b32 = (size_t)gw * (2 * F) + lane;   // uint32 units, F/2 per segment
        uint32_t hi, lo;
        split2(mean0, mean1, hi, lo); Ah[b32] = hi;               Al[b32] = lo;
        split2(mn0, mn1, hi, lo);     Ah[b32 + F / 2] = hi;       Al[b32 + F / 2] = lo;
        split2(mx0, mx1, hi, lo);     Ah[b32 + F] = hi;           Al[b32 + F] = lo;
        split2(sd0, sd1, hi, lo);     Ah[b32 + 3 * F / 2] = hi;   Al[b32 + 3 * F / 2] = lo;
    }
    if (F == 96) {
        __nv_bfloat16* Ah16 = (__nv_bfloat16*)g_Ah_;
        __nv_bfloat16* Al16 = (__nv_bfloat16*)g_Al_;
        float mean2 = sm2 * inv;
        float sd2 = sqrtf(fmaxf(ss2 * inv - mean2 * mean2, 0.f) + STD_EPS);
        size_t be = (size_t)gw * (4 * F) + 64 + lane;
        float vals[4] = {mean2, mn2, mx2, sd2};
        #pragma unroll
        for (int q = 0; q < 4; q++) {
            __nv_bfloat16 hv = __float2bfloat16(vals[q]);
            Ah16[be + q * F] = hv;
            Al16[be + q * F] = __float2bfloat16(vals[q] - __bfloat162float(hv));
        }
    }
    if (F == 32) {
        __nv_bfloat16* Ah16 = (__nv_bfloat16*)g_Ah_;
        __nv_bfloat16* Al16 = (__nv_bfloat16*)g_Al_;
        float mean0 = sm0 * inv;
        float sd0 = sqrtf(fmaxf(ss0 * inv - mean0 * mean0, 0.f) + STD_EPS);
        size_t be = (size_t)gw * (4 * F) + lane;
        float vals[4] = {mean0, mn0, mx0, sd0};
        #pragma unroll
        for (int q = 0; q < 4; q++) {
            __nv_bfloat16 hv = __float2bfloat16(vals[q]);
            Ah16[be + q * F] = hv;
            Al16[be + q * F] = __float2bfloat16(vals[q] - __bfloat162float(hv));
        }
    }
}

// ---------------- weight pre-split: W[13F,FO] -> 3 slabs [3*FOP][K5P] bf16 hi/lo ----
__global__ void k_wsplit(const float* __restrict__ W, int F, int FO, int FOP, int K5P) {
    int K5 = 5 * F;
    int total = 3 * FOP * K5P;
    int idx = blockIdx.x * blockDim.x + threadIdx.x;
    if (idx >= total) return;
    int row = idx / K5P, k = idx - row * K5P;
    int j = row / FOP, o = row - j * FOP;
    float v = 0.0f;
    if (o < FO && k < K5) {
        if (j == 0) v = W[(size_t)k * FO + o];
        else if (k >= F) v = W[(size_t)(4 * F * j + k) * FO + o];
    }
    __nv_bfloat16 hi = __float2bfloat16(v);
    float r = v - __bfloat162float(hi);
    g_Wth[idx] = hi;
    g_Wtl[idx] = __float2bfloat16(r);
}

// ---------------- mma.sync fused PNA GEMM (3 accumulator sets, pre-split A) -------
// A' = [Xhl | Ahl] (5F wide, already bf16 hi/lo). acc0 = A'@W0', acc1 = agg@W2, acc2 = agg@W3.
// out = acc0 + s1*acc1 + s2*acc2 + bias (optional relu). Optionally writes bf16 hi/lo of out.
template <int NT, int CS>
__global__ __launch_bounds__(256) void k_mma_gemm(
    const __nv_bfloat16* __restrict__ Xh, const __nv_bfloat16* __restrict__ Xl,
    const __nv_bfloat16* __restrict__ Wth, const __nv_bfloat16* __restrict__ Wtl,
    const float* __restrict__ bias, float* __restrict__ out,
    uint32_t* __restrict__ wbh, uint32_t* __restrict__ wbl,
    int F, int FO, int K5P, int relu)
{
    const int RW = 8 / CS;
    const int M = RW * 16;
    const int FOP = NT * 8 * CS;
    const int K5 = 5 * F;
    const int NCH = K5P >> 6;
    extern __shared__ char smem_raw[];
    uint32_t base = (smem_u32(smem_raw) + 1023u) & ~1023u;
    uint32_t AHI = base;
    uint32_t ALO = AHI + (uint32_t)(M * 128);
    uint32_t BHI = ALO + (uint32_t)(M * 128);
    uint32_t BLO = BHI + (uint32_t)(3 * FOP * 128);

    const __nv_bfloat16* Ah = (const __nv_bfloat16*)g_Ah_;
    const __nv_bfloat16* Al = (const __nv_bfloat16*)g_Al_;

    int tid = threadIdx.x;
    int wid = tid >> 5, lane = tid & 31;
    int warpRow = wid % RW, warpCol = wid / RW;
    int nbase = blockIdx.x * M;
    int r16 = lane & 15, c4 = lane >> 4;

    float acc[3][NT][4];
    #pragma unroll
    for (int j = 0; j < 3; j++)
        #pragma unroll
        for (int t = 0; t < NT; t++) {
            acc[j][t][0] = 0.f; acc[j][t][1] = 0.f;
            acc[j][t][2] = 0.f; acc[j][t][3] = 0.f;
        }

    for (int c = 0; c < NCH; c++) {
        int hasAgg = ((c + 1) * 64 > F);
        int nslab = hasAgg ? 3 : 1;
        __syncthreads();
        // ---- A' tile: pure copy of pre-split bf16 hi/lo into SW128 smem ----
        for (int p = tid; p < M * 8; p += 256) {
            int row = p >> 3, g = p & 7;
            int n = nbase + row;
            int k = c * 64 + g * 8;
            uint4 vh = make_uint4(0u, 0u, 0u, 0u), vl = vh;
            if (n < N_NODES && k < K5) {
                if (k < F) {
                    size_t o = (size_t)n * F + k;
                    vh = *(const uint4*)(Xh + o);
                    vl = *(const uint4*)(Xl + o);
                } else {
                    size_t o = (size_t)n * (4 * F) + (k - F);
                    vh = *(const uint4*)(Ah + o);
                    vl = *(const uint4*)(Al + o);
                }
            }
            uint32_t off = swz((uint32_t)(row * 128 + g * 16));
            sts128(AHI + off, vh.x, vh.y, vh.z, vh.w);
            sts128(ALO + off, vl.x, vl.y, vl.z, vl.w);
        }
        for (int p = tid; p < nslab * FOP * 8; p += 256) {
            int row = p >> 3, g = p & 7;
            int k = c * 64 + g * 8;
            uint4 vh = *(const uint4*)(Wth + (size_t)row * K5P + k);
            uint4 vl = *(const uint4*)(Wtl + (size_t)row * K5P + k);
            uint32_t off = swz((uint32_t)(row * 128 + g * 16));
            sts128(BHI + off, vh.x, vh.y, vh.z, vh.w);
            sts128(BLO + off, vl.x, vl.y, vl.z, vl.w);
        }
        __syncthreads();
        #pragma unroll
        for (int ks = 0; ks < 4; ks++) {
            uint32_t aoff = swz((uint32_t)((warpRow * 16 + r16) * 128 + ks * 32 + c4 * 16));
            uint32_t ah[4], al[4];
            ldsm4(ah, AHI + aoff);
            ldsm4(al, ALO + aoff);
            #pragma unroll
            for (int j = 0; j < 3; j++) {
                if (j > 0 && !hasAgg) continue;
                #pragma unroll
                for (int nt2 = 0; nt2 < NT / 2; nt2++) {
                    int brow = j * FOP + warpCol * NT * 8 + nt2 * 16;
                    uint32_t boff = swz((uint32_t)((brow + r16) * 128 + ks * 32 + c4 * 16));
                    uint32_t bh[4], bl[4];
                    ldsm4(bh, BHI + boff);
                    ldsm4(bl, BLO + boff);
                    int t0 = nt2 * 2, t1 = t0 + 1;
                    mma16816(acc[j][t0], ah, bh[0], bh[2]);
                    mma16816(acc[j][t0], ah, bl[0], bl[2]);
                    mma16816(acc[j][t0], al, bh[0], bh[2]);
                    mma16816(acc[j][t1], ah, bh[1], bh[3]);
                    mma16816(acc[j][t1], ah, bl[1], bl[3]);
                    mma16816(acc[j][t1], al, bh[1], bh[3]);
                }
            }
        }
    }
    int n0 = nbase + warpRow * 16 + (lane >> 2);
    int n1 = n0 + 8;
    int cb = (lane & 3) * 2;
    float s1a = 0.f, s2a = 0.f, s1b = 0.f, s2b = 0.f;
    if (n0 < N_NODES) { s1a = g_s1[n0]; s2a = g_s2[n0]; }
    if (n1 < N_NODES) { s1b = g_s1[n1]; s2b = g_s2[n1]; }
    #pragma unroll
    for (int t = 0; t < NT; t++) {
        int col = warpCol * NT * 8 + t * 8 + cb;
        if (col < FO) {
            float b0 = bias[col];
            float b1 = (col + 1 < FO) ? bias[col + 1] : 0.f;
            if (n0 < N_NODES) {
                float u0 = acc[0][t][0] + s1a * acc[1][t][0] + s2a * acc[2][t][0] + b0;
                float u1 = acc[0][t][1] + s1a * acc[1][t][1] + s2a * acc[2][t][1] + b1;
                if (relu) { u0 = fmaxf(u0, 0.f); u1 = fmaxf(u1, 0.f); }
                out[(size_t)n0 * FO + col] = u0;
                if (col + 1 < FO) out[(size_t)n0 * FO + col + 1] = u1;
                if (wbh) {
                    uint32_t hi, lo;
                    split2(u0, u1, hi, lo);
                    size_t oi = ((size_t)n0 * FO + col) >> 1;
                    wbh[oi] = hi; wbl[oi] = lo;
                }
            }
            if (n1 < N_NODES) {
                float u2 = acc[0][t][2] + s1b * acc[1][t][2] + s2b * acc[2][t][2] + b0;
                float u3 = acc[0][t][3] + s1b * acc[1][t][3] + s2b * acc[2][t][3] + b1;
                if (relu) { u2 = fmaxf(u2, 0.f); u3 = fmaxf(u3, 0.f); }
                out[(size_t)n1 * FO + col] = u2;
                if (col + 1 < FO) out[(size_t)n1 * FO + col + 1] = u3;
                if (wbh) {
                    uint32_t hi, lo;
                    split2(u2, u3, hi, lo);
                    size_t oi = ((size_t)n1 * FO + col) >> 1;
                    wbh[oi] = hi; wbl[oi] = lo;
                }
            }
        }
    }
}

// ---------------- batch norm (deterministic 2-stage stats) ----------------
template <int C>
__global__ void k_bnstats(const float* __restrict__ Y) {
    __shared__ float shs[4][C];
    __shared__ float shss[4][C];
    int c = threadIdx.x, y = threadIdx.y;
    int n0 = blockIdx.x * 1024;
    int n1 = min(N_NODES, n0 + 1024);
    float s = 0.0f, ss = 0.0f;
    for (int n = n0 + y; n < n1; n += 4) {
        float v = Y[(size_t)n * C + c];
        s += v; ss += v * v;
    }
    shs[y][c] = s; shss[y][c] = ss;
    __syncthreads();
    if (y == 0) {
        float S  = shs[0][c] + shs[1][c] + shs[2][c] + shs[3][c];
        float SS = shss[0][c] + shss[1][c] + shss[2][c] + shss[3][c];
        g_part[blockIdx.x * 2 * C + c]     = S;
        g_part[blockIdx.x * 2 * C + C + c] = SS;
    }
}
template <int C>
__global__ void k_bnfin(const float* __restrict__ g, const float* __restrict__ be, int nb) {
    int c = threadIdx.x;
    if (c >= C) return;
    float s = 0.0f, ss = 0.0f;
    for (int i = 0; i < nb; i++) {
        s  += g_part[i * 2 * C + c];
        ss += g_part[i * 2 * C + C + c];
    }
    float mu = s / (float)N_NODES;
    float var = ss / (float)N_NODES - mu * mu;
    float sc = g[c] * rsqrtf(var + BN_EPS);
    g_scale[c] = sc;
    g_shift[c] = be[c] - mu * sc;
}
// bnapply + relu + bf16 hi/lo writeback (C even, processes 2 elems/thread)
template <int C>
__global__ void k_bnapply_b16(float* __restrict__ Y, uint32_t* __restrict__ xh,
                              uint32_t* __restrict__ xl) {
    int i = blockIdx.x * blockDim.x + threadIdx.x;
    if (i < N_NODES * C / 2) {
        int e = 2 * i;
        int c = e % C;
        float v0 = fmaxf(fmaf(Y[e], g_scale[c], g_shift[c]), 0.0f);
        float v1 = fmaxf(fmaf(Y[e + 1], g_scale[c + 1], g_shift[c + 1]), 0.0f);
        Y[e] = v0; Y[e + 1] = v1;
        uint32_t hi, lo;
        split2(v0, v1, hi, lo);
        xh[i] = hi; xl[i] = lo;
    }
}
template <int C, bool RELU>
__global__ void k_bnapply(float* __restrict__ Y) {
    int i = blockIdx.x * blockDim.x + threadIdx.x;
    if (i < N_NODES * C) {
        int c = i % C;
        float v = fmaf(Y[i], g_scale[c], g_shift[c]);
        if (RELU) v = fmaxf(v, 0.0f);
        Y[i] = v;
    }
}

// ---------------- pooling + classifier head ----------------
__global__ void k_pool(const float* __restrict__ h, float* __restrict__ outz, int write_out) {
    int g = blockIdx.x;
    int c = threadIdx.x, y = threadIdx.y;
    int s = g_gstart[g], e = g_gstart[g + 1];
    float acc = 0.0f;
    if (c < 20)
        for (int n = s + y; n < e; n += 8) acc += h[(size_t)n * 20 + c];
    __shared__ float sh[8][32];
    sh[y][c] = acc;
    __syncthreads();
    if (y == 0 && c < 20) {
        float S = 0.0f;
        #pragma unroll
        for (int k = 0; k < 8; k++) S += sh[k][c];
        float cntf = fmaxf((float)(e - s), 1.0f);
        float z = S / cntf;
        g_z[g * 20 + c] = z;
        if (write_out) outz[g * 20 + c] = z;
    }
}
__global__ void k_final(const float* __restrict__ wlin, const float* __restrict__ blin,
                        float* __restrict__ out) {
    int g = blockIdx.x;
    int o = threadIdx.x;
    float l = -INFINITY;
    if (o < 11) {
        float s = blin[o];
        for (int k = 0; k < 20; k++) s = fmaf(g_z[g * 20 + k], wlin[k * 11 + o], s);
        l = s;
    }
    float m = l;
    #pragma unroll
    for (int off = 16; off; off >>= 1) m = fmaxf(m, __shfl_xor_sync(0xffffffffu, m, off));
    float ex = (o < 11) ? expf(l - m) : 0.0f;
    float sum = ex;
    #pragma unroll
    for (int off = 16; off; off >>= 1) sum += __shfl_xor_sync(0xffffffffu, sum, off);
    if (o < 11) out[g * 11 + o] = ex / sum;
}

// ---------------- host ----------------
extern "C" void kernel_launch(void* const* d_in, const int* in_sizes, int n_in,
                              void* d_out, int out_size) {
    const float* x     = (const float*)d_in[0];
    const int*   ei    = (const int*)d_in[1];
    const int*   batch = (const int*)d_in[2];
    const float* w0 = (const float*)d_in[3];  const float* b0 = (const float*)d_in[4];
    const float* w1 = (const float*)d_in[5];  const float* b1 = (const float*)d_in[6];
    const float* w2 = (const float*)d_in[7];  const float* b2 = (const float*)d_in[8];
    const float* w3 = (const float*)d_in[9];  const float* b3 = (const float*)d_in[10];
    const float* g0 = (const float*)d_in[11]; const float* be0 = (const float*)d_in[12];
    const float* g1 = (const float*)d_in[13]; const float* be1 = (const float*)d_in[14];
    const float* g2 = (const float*)d_in[15]; const float* be2 = (const float*)d_in[16];
    const float* wlin = (const float*)d_in[17]; const float* blin = (const float*)d_in[18];
    float* out = (float*)d_out;

    const int* src = ei;
    const int* dst = ei + N_EDGES;

    float *hA, *hB;
    __nv_bfloat16 *wth, *wtl;
    void *xh0, *xl0, *xh1, *xl1;
    cudaGetSymbolAddress((void**)&hA, g_hA);
    cudaGetSymbolAddress((void**)&hB, g_hB);
    cudaGetSymbolAddress((void**)&wth, g_Wth);
    cudaGetSymbolAddress((void**)&wtl, g_Wtl);
    cudaGetSymbolAddress(&xh0, g_Xh0_);
    cudaGetSymbolAddress(&xl0, g_Xl0_);
    cudaGetSymbolAddress(&xh1, g_Xh1_);
    cudaGetSymbolAddress(&xl1, g_Xl1_);

    int nbE = (N_EDGES + 255) / 256;
    int nbN = (N_NODES + 255) / 256;

    const int SM_L0 = 1024 + 2 * 64 * 128 + 2 * 3 * 96 * 128;    // <6,2>
    const int SM_L1 = 1024 + 2 * 128 * 128 + 2 * 3 * 64 * 128;   // <8,1>
    const int SM_L23 = 1024 + 2 * 128 * 128 + 2 * 3 * 32 * 128;  // <4,1>
    typedef void (*gemm_fn)(const __nv_bfloat16*, const __nv_bfloat16*,
                            const __nv_bfloat16*, const __nv_bfloat16*,
                            const float*, float*, uint32_t*, uint32_t*,
                            int, int, int, int);
    gemm_fn f62 = k_mma_gemm<6, 2>;
    gemm_fn f81 = k_mma_gemm<8, 1>;
    gemm_fn f41 = k_mma_gemm<4, 1>;
    cudaFuncSetAttribute((const void*)f62, cudaFuncAttributeMaxDynamicSharedMemorySize, SM_L0);
    cudaFuncSetAttribute((const void*)f81, cudaFuncAttributeMaxDynamicSharedMemorySize, SM_L1);
    cudaFuncSetAttribute((const void*)f41, cudaFuncAttributeMaxDynamicSharedMemorySize, SM_L23);

    // CSR + per-node scalers
    k_zero<<<nbN, 256>>>();
    k_hist<<<nbE, 256>>>(dst);
    k_scanA<<<NB_SCAN, 1024>>>();
    k_scanB<<<NB_SCAN, 1024>>>();
    k_scatter<<<nbE, 256>>>(src, dst);
    k_s1s2b<<<nbN, 256>>>(batch);

    const int NBST = (N_NODES + 1023) / 1024;
    const int GB64  = (N_NODES + 63) / 64;
    const int GB128 = (N_NODES + 127) / 128;
    const int AGGB  = (N_NODES * 32 + 255) / 256;

    const int K5P0 = 320;   // F=64
    const int K5P1 = 512;   // F=96
    const int K5P3 = 192;   // F=32

    // Layer 0: 64 -> 96, BN + relu
    k_convx<<<(N_NODES * 32 + 255) / 256, 256>>>(x, (uint32_t*)xh0, (uint32_t*)xl0, N_NODES * 32);
    k_wsplit<<<(3 * 96 * K5P0 + 255) / 256, 256>>>(w0, 64, 96, 96, K5P0);
    k_agg<64><<<AGGB, 256>>>(x);
    k_mma_gemm<6, 2><<<GB64, 256, SM_L0>>>((__nv_bfloat16*)xh0, (__nv_bfloat16*)xl0,
                                           wth, wtl, b0, hA, 0, 0, 64, 96, K5P0, 0);
    k_bnstats<96><<<NBST, dim3(96, 4)>>>(hA);
    k_bnfin<96><<<1, 96>>>(g0, be0, NBST);
    k_bnapply_b16<96><<<(N_NODES * 48 + 255) / 256, 256>>>(hA, (uint32_t*)xh1, (uint32_t*)xl1);

    // Layer 1: 96 -> 64, BN + relu
    k_wsplit<<<(3 * 64 * K5P1 + 255) / 256, 256>>>(w1, 96, 64, 64, K5P1);
    k_agg<96><<<AGGB, 256>>>(hA);
    k_mma_gemm<8, 1><<<GB128, 256, SM_L1>>>((__nv_bfloat16*)xh1, (__nv_bfloat16*)xl1,
                                            wth, wtl, b1, hB, 0, 0, 96, 64, K5P1, 0);
    k_bnstats<64><<<NBST, dim3(64, 4)>>>(hB);
    k_bnfin<64><<<1, 64>>>(g1, be1, NBST);
    k_bnapply_b16<64><<<(N_NODES * 32 + 255) / 256, 256>>>(hB, (uint32_t*)xh0, (uint32_t*)xl0);

    // Layer 2: 64 -> 32, relu fused; epilogue also writes bf16 hi/lo for layer 3
    k_wsplit<<<(3 * 32 * K5P0 + 255) / 256, 256>>>(w2, 64, 32, 32, K5P0);
    k_agg<64><<<AGGB, 256>>>(hB);
    k_mma_gemm<4, 1><<<GB128, 256, SM_L23>>>((__nv_bfloat16*)xh0, (__nv_bfloat16*)xl0,
                                             wth, wtl, b2, hA,
                                             (uint32_t*)xh1, (uint32_t*)xl1, 64, 32, K5P0, 1);

    // Layer 3: 32 -> 20, BN (no relu)
    k_wsplit<<<(3 * 32 * K5P3 + 255) / 256, 256>>>(w3, 32, 20, 32, K5P3);
    k_agg<32><<<AGGB, 256>>>(hA);
    k_mma_gemm<4, 1><<<GB128, 256, SM_L23>>>((__nv_bfloat16*)xh1, (__nv_bfloat16*)xl1,
                                             wth, wtl, b3, hB, 0, 0, 32, 20, K5P3, 0);
    k_bnstats<20><<<NBST, dim3(20, 4)>>>(hB);
    k_bnfin<20><<<1, 20>>>(g2, be2, NBST);
    k_bnapply<20, false><<<(N_NODES * 20 + 255) / 256, 256>>>(hB);

    // Pool + head. Output layout: [softmax out (64x11) | z (64x20)]
    int write_z = (out_size >= 64 * 11 + 64 * 20) ? 1 : 0;
    k_pool<<<N_GRAPH, dim3(32, 8)>>>(hB, out + 64 * 11, write_z);
    k_final<<<N_GRAPH, 32>>>(wlin, blin, out);
}

// round 16
// speedup vs baseline: 2.1455x; 1.0150x over previous
#include <cuda_runtime.h>
#include <cuda_bf16.h>
#include <stdint.h>
#include <math.h>

#define N_NODES 100000
#define N_EDGES 3200000
#define N_GRAPH 64
#define AVG_LOG 3.4965075614664802f
#define BN_EPS 1e-5f
#define STD_EPS 1e-5f
#define NB_SCAN 98    // ceil(N_NODES/1024)

// ---------------- scratch (device globals; no allocation allowed) ----------------
__device__ int   g_deg[N_NODES];
__device__ int   g_rowp[N_NODES + 1];
__device__ int   g_cur[N_NODES];
__device__ int   g_csr[N_EDGES];
__device__ int   g_bsum[NB_SCAN];
__device__ float g_s1[N_NODES];
__device__ float g_s2[N_NODES];
__device__ float g_hA[(size_t)N_NODES * 96];
__device__ float g_hB[(size_t)N_NODES * 96];
__device__ float g_colS[96];                   // BN column sums (epilogue atomics)
__device__ float g_colSS[96];
__device__ float g_scale[96];
__device__ float g_shift[96];
__device__ int   g_gstart[N_GRAPH + 1];
__device__ __nv_bfloat16 g_Wth[3 * 96 * 512];  // weight bf16-hi, [3*FOP][K5P]
__device__ __nv_bfloat16 g_Wtl[3 * 96 * 512];  // weight bf16-lo
// bf16 hi/lo activation + agg buffers (uint4-typed for 16B alignment)
__device__ uint4 g_Ah_[(size_t)N_NODES * 48];  // agg hi: N x 4F (F<=96) bf16
__device__ uint4 g_Al_[(size_t)N_NODES * 48];  // agg lo
__device__ uint4 g_Xh0_[(size_t)N_NODES * 12]; // act hi set0: N x 96 bf16
__device__ uint4 g_Xl0_[(size_t)N_NODES * 12];
__device__ uint4 g_Xh1_[(size_t)N_NODES * 12]; // act hi set1
__device__ uint4 g_Xl1_[(size_t)N_NODES * 12];

// ---------------- helpers (base-ISA only: ldmatrix + mma.sync) ----------------
__device__ __forceinline__ uint32_t smem_u32(const void* p) {
    uint32_t a;
    asm("{ .reg .u64 t; cvta.to.shared.u64 t, %1; cvt.u32.u64 %0, t; }" : "=r"(a) : "l"(p));
    return a;
}
__device__ __forceinline__ void ldsm4(uint32_t* r, uint32_t addr) {
    asm volatile("ldmatrix.sync.aligned.m8n8.x4.shared.b16 {%0,%1,%2,%3}, [%4];"
        : "=r"(r[0]), "=r"(r[1]), "=r"(r[2]), "=r"(r[3]) : "r"(addr));
}
__device__ __forceinline__ void mma16816(float* d, const uint32_t* a, uint32_t b0, uint32_t b1) {
    asm volatile(
        "mma.sync.aligned.m16n8k16.row.col.f32.bf16.bf16.f32 "
        "{%0,%1,%2,%3}, {%4,%5,%6,%7}, {%8,%9}, {%0,%1,%2,%3};"
        : "+f"(d[0]), "+f"(d[1]), "+f"(d[2]), "+f"(d[3])
        : "r"(a[0]), "r"(a[1]), "r"(a[2]), "r"(a[3]), "r"(b0), "r"(b1));
}
__device__ __forceinline__ void sts128(uint32_t a, uint32_t x, uint32_t y, uint32_t z, uint32_t w) {
    asm volatile("st.shared.v4.b32 [%0], {%1,%2,%3,%4};" :: "r"(a), "r"(x), "r"(y), "r"(z), "r"(w) : "memory");
}
__device__ __forceinline__ uint32_t swz(uint32_t off) { return off ^ ((off >> 3) & 0x70); }
__device__ __forceinline__ uint32_t pack2(__nv_bfloat16 a, __nv_bfloat16 b) {
    return (uint32_t)__bfloat16_as_ushort(a) | ((uint32_t)__bfloat16_as_ushort(b) << 16);
}
// split two fp32 into packed bf16 hi + packed bf16 lo
__device__ __forceinline__ void split2(float v0, float v1, uint32_t& hi, uint32_t& lo) {
    __nv_bfloat16 h0 = __float2bfloat16(v0);
    __nv_bfloat16 h1 = __float2bfloat16(v1);
    hi = pack2(h0, h1);
    lo = pack2(__float2bfloat16(v0 - __bfloat162float(h0)),
               __float2bfloat16(v1 - __bfloat162float(h1)));
}

// ---------------- input convert (+ degree zero) ----------------
__global__ void k_convx(const float* __restrict__ x, uint32_t* __restrict__ xh,
                        uint32_t* __restrict__ xl, int total2) {
    int i = blockIdx.x * blockDim.x + threadIdx.x;
    if (i < total2) {
        float2 v = *(const float2*)(x + 2 * i);
        uint32_t hi, lo;
        split2(v.x, v.y, hi, lo);
        xh[i] = hi; xl[i] = lo;
    }
    if (i < N_NODES) { g_deg[i] = 0; g_cur[i] = 0; }
}
__global__ void k_hist(const int* __restrict__ dst) {
    int e = blockIdx.x * blockDim.x + threadIdx.x;
    if (e < N_EDGES) atomicAdd(&g_deg[dst[e]], 1);
}
// multi-block scan: per-block local exclusive prefix + block totals
__global__ void k_scanA() {
    __shared__ int warpsum[32];
    int tid = threadIdx.x, lane = tid & 31, wid = tid >> 5;
    int i = blockIdx.x * 1024 + tid;
    int v = (i < N_NODES) ? g_deg[i] : 0;
    int x = v;
    #pragma unroll
    for (int off = 1; off < 32; off <<= 1) {
        int y = __shfl_up_sync(0xffffffffu, x, off);
        if (lane >= off) x += y;
    }
    if (lane == 31) warpsum[wid] = x;
    __syncthreads();
    if (wid == 0) {
        int w = warpsum[lane];
        #pragma unroll
        for (int off = 1; off < 32; off <<= 1) {
            int y = __shfl_up_sync(0xffffffffu, w, off);
            if (lane >= off) w += y;
        }
        warpsum[lane] = w;
    }
    __syncthreads();
    int excl = x - v + (wid > 0 ? warpsum[wid - 1] : 0);
    if (i < N_NODES) g_rowp[i] = excl;
    if (tid == 1023) g_bsum[blockIdx.x] = excl + v;
}
// scan finalize + per-node scalers + graph boundaries (merged)
__global__ void k_scanB(const int* __restrict__ batch) {
    __shared__ int s_off;
    if (threadIdx.x == 0) {
        int o = 0;
        for (int b = 0; b < (int)blockIdx.x; b++) o += g_bsum[b];
        s_off = o;
    }
    __syncthreads();
    int i = blockIdx.x * 1024 + threadIdx.x;
    if (i < N_NODES) {
        g_rowp[i] += s_off;
        float degc = fmaxf((float)g_deg[i], 1.0f);
        float logd = logf(degc + 1.0f);
        g_s1[i] = logd / AVG_LOG;
        g_s2[i] = AVG_LOG / logd;
        if (i == 0) {
            for (int g = 0; g <= batch[0]; g++) g_gstart[g] = 0;
        } else {
            int b0 = batch[i - 1], b1 = batch[i];
            if (b1 != b0) for (int g = b0 + 1; g <= b1; g++) g_gstart[g] = i;
        }
        if (i == N_NODES - 1) {
            for (int g = batch[i] + 1; g <= N_GRAPH; g++) g_gstart[g] = N_NODES;
        }
    }
    if (i == 0) g_rowp[N_NODES] = N_EDGES;
}
__global__ void k_scatter(const int* __restrict__ src, const int* __restrict__ dst) {
    int e = blockIdx.x * blockDim.x + threadIdx.x;
    if (e < N_EDGES) {
        int d = dst[e];
        int pos = atomicAdd(&g_cur[d], 1);
        g_csr[g_rowp[d] + pos] = src[e];
    }
}

// ---------------- aggregation: warp-per-node, writes bf16 hi/lo directly ----------------
template <int F>
__global__ void __launch_bounds__(256) k_agg(const float* __restrict__ h) {
    int gw = (blockIdx.x * 256 + threadIdx.x) >> 5;
    if (gw >= N_NODES) return;
    int lane = threadIdx.x & 31;
    int s = g_rowp[gw], e = g_rowp[gw + 1];
    int deg = e - s;

    float sm0 = 0.f, sm1 = 0.f, sm2 = 0.f;
    float ss0 = 0.f, ss1 = 0.f, ss2 = 0.f;
    float mn0 = INFINITY, mn1 = INFINITY, mn2 = INFINITY;
    float mx0 = -INFINITY, mx1 = -INFINITY, mx2 = -INFINITY;

    for (int c0 = s; c0 < e; c0 += 32) {
        int m = e - c0; if (m > 32) m = 32;
        int nb = (lane < m) ? g_csr[c0 + lane] : 0;
        for (int j = 0; j < m; j++) {
            int idx = __shfl_sync(0xffffffffu, nb, j);
            const float* row = h + (size_t)idx * F;
            if (F >= 64) {
                float2 v = *(const float2*)(row + 2 * lane);
                sm0 += v.x; ss0 = fmaf(v.x, v.x, ss0);
                mn0 = fminf(mn0, v.x); mx0 = fmaxf(mx0, v.x);
                sm1 += v.y; ss1 = fmaf(v.y, v.y, ss1);
                mn1 = fminf(mn1, v.y); mx1 = fmaxf(mx1, v.y);
            }
            if (F == 96) {
                float v = row[64 + lane];
                sm2 += v; ss2 = fmaf(v, v, ss2);
                mn2 = fminf(mn2, v); mx2 = fmaxf(mx2, v);
            }
            if (F == 32) {
                float v = row[lane];
                sm0 += v; ss0 = fmaf(v, v, ss0);
                mn0 = fminf(mn0, v); mx0 = fmaxf(mx0, v);
            }
        }
    }
    float degc = fmaxf((float)deg, 1.0f);
    float inv = 1.0f / degc;
    if (deg == 0) {
        mn0 = 0.f; mx0 = 0.f; mn1 = 0.f; mx1 = 0.f; mn2 = 0.f; mx2 = 0.f;
    }
    uint32_t* Ah = (uint32_t*)g_Ah_;
    uint32_t* Al = (uint32_t*)g_Al_;
    if (F >= 64) {
        float mean0 = sm0 * inv, mean1 = sm1 * inv;
        float sd0 = sqrtf(fmaxf(ss0 * inv - mean0 * mean0, 0.f) + STD_EPS);
        float sd1 = sqrtf(fmaxf(ss1 * inv - mean1 * mean1, 0.f) + STD_EPS);
        size_t b32 = (size_t)gw * (2 * F) + lane;
        uint32_t hi, lo;
        split2(mean0, mean1, hi, lo); Ah[b32] = hi;               Al[b32] = lo;
        split2(mn0, mn1, hi, lo);     Ah[b32 + F / 2] = hi;       Al[b32 + F / 2] = lo;
        split2(mx0, mx1, hi, lo);     Ah[b32 + F] = hi;           Al[b32 + F] = lo;
        split2(sd0, sd1, hi, lo);     Ah[b32 + 3 * F / 2] = hi;   Al[b32 + 3 * F / 2] = lo;
    }
    if (F == 96) {
        __nv_bfloat16* Ah16 = (__nv_bfloat16*)g_Ah_;
        __nv_bfloat16* Al16 = (__nv_bfloat16*)g_Al_;
        float mean2 = sm2 * inv;
        float sd2 = sqrtf(fmaxf(ss2 * inv - mean2 * mean2, 0.f) + STD_EPS);
        size_t be = (size_t)gw * (4 * F) + 64 + lane;
        float vals[4] = {mean2, mn2, mx2, sd2};
        #pragma unroll
        for (int q = 0; q < 4; q++) {
            __nv_bfloat16 hv = __float2bfloat16(vals[q]);
            Ah16[be + q * F] = hv;
            Al16[be + q * F] = __float2bfloat16(vals[q] - __bfloat162float(hv));
        }
    }
    if (F == 32) {
        __nv_bfloat16* Ah16 = (__nv_bfloat16*)g_Ah_;
        __nv_bfloat16* Al16 = (__nv_bfloat16*)g_Al_;
        float mean0 = sm0 * inv;
        float sd0 = sqrtf(fmaxf(ss0 * inv - mean0 * mean0, 0.f) + STD_EPS);
        size_t be = (size_t)gw * (4 * F) + lane;
        float vals[4] = {mean0, mn0, mx0, sd0};
        #pragma unroll
        for (int q = 0; q < 4; q++) {
            __nv_bfloat16 hv = __float2bfloat16(vals[q]);
            Ah16[be + q * F] = hv;
            Al16[be + q * F] = __float2bfloat16(vals[q] - __bfloat162float(hv));
        }
    }
}

// ---------------- weight pre-split (+ BN column-sum zeroing) ----------------
__global__ void k_wsplit(const float* __restrict__ W, int F, int FO, int FOP, int K5P) {
    int idx = blockIdx.x * blockDim.x + threadIdx.x;
    if (idx < 96) { g_colS[idx] = 0.f; g_colSS[idx] = 0.f; }
    int K5 = 5 * F;
    int total = 3 * FOP * K5P;
    if (idx >= total) return;
    int row = idx / K5P, k = idx - row * K5P;
    int j = row / FOP, o = row - j * FOP;
    float v = 0.0f;
    if (o < FO && k < K5) {
        if (j == 0) v = W[(size_t)k * FO + o];
        else if (k >= F) v = W[(size_t)(4 * F * j + k) * FO + o];
    }
    __nv_bfloat16 hi = __float2bfloat16(v);
    float r = v - __bfloat162float(hi);
    g_Wth[idx] = hi;
    g_Wtl[idx] = __float2bfloat16(r);
}

// ---------------- mma.sync fused PNA GEMM (3 acc sets, pre-split A, fused BN stats) ----
template <int NT, int CS>
__global__ __launch_bounds__(256) void k_mma_gemm(
    const __nv_bfloat16* __restrict__ Xh, const __nv_bfloat16* __restrict__ Xl,
    const __nv_bfloat16* __restrict__ Wth, const __nv_bfloat16* __restrict__ Wtl,
    const float* __restrict__ bias, float* __restrict__ out,
    uint32_t* __restrict__ wbh, uint32_t* __restrict__ wbl,
    int F, int FO, int K5P, int relu, int stats)
{
    const int RW = 8 / CS;
    const int M = RW * 16;
    const int FOP = NT * 8 * CS;
    const int K5 = 5 * F;
    const int NCH = K5P >> 6;
    extern __shared__ char smem_raw[];
    uint32_t base = (smem_u32(smem_raw) + 1023u) & ~1023u;
    uint32_t AHI = base;
    uint32_t ALO = AHI + (uint32_t)(M * 128);
    uint32_t BHI = ALO + (uint32_t)(M * 128);
    uint32_t BLO = BHI + (uint32_t)(3 * FOP * 128);

    const __nv_bfloat16* Ah = (const __nv_bfloat16*)g_Ah_;
    const __nv_bfloat16* Al = (const __nv_bfloat16*)g_Al_;

    int tid = threadIdx.x;
    int wid = tid >> 5, lane = tid & 31;
    int warpRow = wid % RW, warpCol = wid / RW;
    int nbase = blockIdx.x * M;
    int r16 = lane & 15, c4 = lane >> 4;

    float acc[3][NT][4];
    #pragma unroll
    for (int j = 0; j < 3; j++)
        #pragma unroll
        for (int t = 0; t < NT; t++) {
            acc[j][t][0] = 0.f; acc[j][t][1] = 0.f;
            acc[j][t][2] = 0.f; acc[j][t][3] = 0.f;
        }

    for (int c = 0; c < NCH; c++) {
        int hasAgg = ((c + 1) * 64 > F);
        int nslab = hasAgg ? 3 : 1;
        __syncthreads();
        for (int p = tid; p < M * 8; p += 256) {
            int row = p >> 3, g = p & 7;
            int n = nbase + row;
            int k = c * 64 + g * 8;
            uint4 vh = make_uint4(0u, 0u, 0u, 0u), vl = vh;
            if (n < N_NODES && k < K5) {
                if (k < F) {
                    size_t o = (size_t)n * F + k;
                    vh = *(const uint4*)(Xh + o);
                    vl = *(const uint4*)(Xl + o);
                } else {
                    size_t o = (size_t)n * (4 * F) + (k - F);
                    vh = *(const uint4*)(Ah + o);
                    vl = *(const uint4*)(Al + o);
                }
            }
            uint32_t off = swz((uint32_t)(row * 128 + g * 16));
            sts128(AHI + off, vh.x, vh.y, vh.z, vh.w);
            sts128(ALO + off, vl.x, vl.y, vl.z, vl.w);
        }
        for (int p = tid; p < nslab * FOP * 8; p += 256) {
            int row = p >> 3, g = p & 7;
            int k = c * 64 + g * 8;
            uint4 vh = *(const uint4*)(Wth + (size_t)row * K5P + k);
            uint4 vl = *(const uint4*)(Wtl + (size_t)row * K5P + k);
            uint32_t off = swz((uint32_t)(row * 128 + g * 16));
            sts128(BHI + off, vh.x, vh.y, vh.z, vh.w);
            sts128(BLO + off, vl.x, vl.y, vl.z, vl.w);
        }
        __syncthreads();
        #pragma unroll
        for (int ks = 0; ks < 4; ks++) {
            uint32_t aoff = swz((uint32_t)((warpRow * 16 + r16) * 128 + ks * 32 + c4 * 16));
            uint32_t ah[4], al[4];
            ldsm4(ah, AHI + aoff);
            ldsm4(al, ALO + aoff);
            #pragma unroll
            for (int j = 0; j < 3; j++) {
                if (j > 0 && !hasAgg) continue;
                #pragma unroll
                for (int nt2 = 0; nt2 < NT / 2; nt2++) {
                    int brow = j * FOP + warpCol * NT * 8 + nt2 * 16;
                    uint32_t boff = swz((uint32_t)((brow + r16) * 128 + ks * 32 + c4 * 16));
                    uint32_t bh[4], bl[4];
                    ldsm4(bh, BHI + boff);
                    ldsm4(bl, BLO + boff);
                    int t0 = nt2 * 2, t1 = t0 + 1;
                    mma16816(acc[j][t0], ah, bh[0], bh[2]);
                    mma16816(acc[j][t0], ah, bl[0], bl[2]);
                    mma16816(acc[j][t0], al, bh[0], bh[2]);
                    mma16816(acc[j][t1], ah, bh[1], bh[3]);
                    mma16816(acc[j][t1], ah, bl[1], bl[3]);
                    mma16816(acc[j][t1], al, bh[1], bh[3]);
                }
            }
        }
    }
    int n0 = nbase + warpRow * 16 + (lane >> 2);
    int n1 = n0 + 8;
    int cb = (lane & 3) * 2;
    bool n0ok = (n0 < N_NODES), n1ok = (n1 < N_NODES);
    float s1a = 0.f, s2a = 0.f, s1b = 0.f, s2b = 0.f;
    if (n0ok) { s1a = g_s1[n0]; s2a = g_s2[n0]; }
    if (n1ok) { s1b = g_s1[n1]; s2b = g_s2[n1]; }
    #pragma unroll
    for (int t = 0; t < NT; t++) {
        int col = warpCol * NT * 8 + t * 8 + cb;
        bool c0 = (col < FO), c1 = (col + 1 < FO);
        float u0 = 0.f, u1 = 0.f, u2 = 0.f, u3 = 0.f;
        if (c0) {
            float b0 = bias[col];
            float b1 = c1 ? bias[col + 1] : 0.f;
            if (n0ok) {
                u0 = acc[0][t][0] + s1a * acc[1][t][0] + s2a * acc[2][t][0] + b0;
                if (relu) u0 = fmaxf(u0, 0.f);
                out[(size_t)n0 * FO + col] = u0;
                if (c1) {
                    u1 = acc[0][t][1] + s1a * acc[1][t][1] + s2a * acc[2][t][1] + b1;
                    if (relu) u1 = fmaxf(u1, 0.f);
                    out[(size_t)n0 * FO + col + 1] = u1;
                }
                if (wbh) {
                    uint32_t hi, lo;
                    split2(u0, u1, hi, lo);
                    size_t oi = ((size_t)n0 * FO + col) >> 1;
                    wbh[oi] = hi; wbl[oi] = lo;
                }
            }
            if (n1ok) {
                u2 = acc[0][t][2] + s1b * acc[1][t][2] + s2b * acc[2][t][2] + b0;
                if (relu) u2 = fmaxf(u2, 0.f);
                out[(size_t)n1 * FO + col] = u2;
                if (c1) {
                    u3 = acc[0][t][3] + s1b * acc[1][t][3] + s2b * acc[2][t][3] + b1;
                    if (relu) u3 = fmaxf(u3, 0.f);
                    out[(size_t)n1 * FO + col + 1] = u3;
                }
                if (wbh) {
                    uint32_t hi, lo;
                    split2(u2, u3, hi, lo);
                    size_t oi = ((size_t)n1 * FO + col) >> 1;
                    wbh[oi] = hi; wbl[oi] = lo;
                }
            }
        }
        if (stats) {
            // column sums over this warp's 16-row stripe via shfl, then fp atomics
            float S0 = u0 + u2, S1 = u1 + u3;
            float Q0 = u0 * u0 + u2 * u2, Q1 = u1 * u1 + u3 * u3;
            #pragma unroll
            for (int off = 4; off < 32; off <<= 1) {
                S0 += __shfl_xor_sync(0xffffffffu, S0, off);
                S1 += __shfl_xor_sync(0xffffffffu, S1, off);
                Q0 += __shfl_xor_sync(0xffffffffu, Q0, off);
                Q1 += __shfl_xor_sync(0xffffffffu, Q1, off);
            }
            if (lane < 4 && c0) {
                atomicAdd(&g_colS[col], S0);
                atomicAdd(&g_colSS[col], Q0);
                if (c1) {
                    atomicAdd(&g_colS[col + 1], S1);
                    atomicAdd(&g_colSS[col + 1], Q1);
                }
            }
        }
    }
}

// ---------------- batch norm finalize + apply ----------------
template <int C>
__global__ void k_bnfin(const float* __restrict__ g, const float* __restrict__ be) {
    int c = threadIdx.x;
    if (c >= C) return;
    float mu = g_colS[c] / (float)N_NODES;
    float var = g_colSS[c] / (float)N_NODES - mu * mu;
    float sc = g[c] * rsqrtf(var + BN_EPS);
    g_scale[c] = sc;
    g_shift[c] = be[c] - mu * sc;
}
// bnapply + relu + bf16 hi/lo writeback (C even, 2 elems/thread)
template <int C>
__global__ void k_bnapply_b16(float* __restrict__ Y, uint32_t* __restrict__ xh,
                              uint32_t* __restrict__ xl) {
    int i = blockIdx.x * blockDim.x + threadIdx.x;
    if (i < N_NODES * C / 2) {
        int e = 2 * i;
        int c = e % C;
        float v0 = fmaxf(fmaf(Y[e], g_scale[c], g_shift[c]), 0.0f);
        float v1 = fmaxf(fmaf(Y[e + 1], g_scale[c + 1], g_shift[c + 1]), 0.0f);
        Y[e] = v0; Y[e + 1] = v1;
        uint32_t hi, lo;
        split2(v0, v1, hi, lo);
        xh[i] = hi; xl[i] = lo;
    }
}
template <int C, bool RELU>
__global__ void k_bnapply(float* __restrict__ Y) {
    int i = blockIdx.x * blockDim.x + threadIdx.x;
    if (i < N_NODES * C) {
        int c = i % C;
        float v = fmaf(Y[i], g_scale[c], g_shift[c]);
        if (RELU) v = fmaxf(v, 0.0f);
        Y[i] = v;
    }
}

// ---------------- fused pooling + classifier head ----------------
__global__ void k_poolfinal(const float* __restrict__ h,
                            const float* __restrict__ wlin, const float* __restrict__ blin,
                            float* __restrict__ out, float* __restrict__ outz, int write_z) {
    int g = blockIdx.x;
    int c = threadIdx.x, y = threadIdx.y;
    int s = g_gstart[g], e = g_gstart[g + 1];
    float acc = 0.0f;
    if (c < 20)
        for (int n = s + y; n < e; n += 8) acc += h[(size_t)n * 20 + c];
    __shared__ float sh[8][32];
    __shared__ float zrow[20];
    sh[y][c] = acc;
    __syncthreads();
    if (y == 0 && c < 20) {
        float S = 0.0f;
        #pragma unroll
        for (int k = 0; k < 8; k++) S += sh[k][c];
        float z = S / fmaxf((float)(e - s), 1.0f);
        zrow[c] = z;
        if (write_z) outz[g * 20 + c] = z;
    }
    __syncthreads();
    if (y == 0) {
        float l = -INFINITY;
        if (c < 11) {
            float s2 = blin[c];
            for (int k = 0; k < 20; k++) s2 = fmaf(zrow[k], wlin[k * 11 + c], s2);
            l = s2;
        }
        float m = l;
        #pragma unroll
        for (int off = 16; off; off >>= 1) m = fmaxf(m, __shfl_xor_sync(0xffffffffu, m, off));
        float ex = (c < 11) ? expf(l - m) : 0.0f;
        float sum = ex;
        #pragma unroll
        for (int off = 16; off; off >>= 1) sum += __shfl_xor_sync(0xffffffffu, sum, off);
        if (c < 11) out[g * 11 + c] = ex / sum;
    }
}

// ---------------- host ----------------
extern "C" void kernel_launch(void* const* d_in, const int* in_sizes, int n_in,
                              void* d_out, int out_size) {
    const float* x     = (const float*)d_in[0];
    const int*   ei    = (const int*)d_in[1];
    const int*   batch = (const int*)d_in[2];
    const float* w0 = (const float*)d_in[3];  const float* b0 = (const float*)d_in[4];
    const float* w1 = (const float*)d_in[5];  const float* b1 = (const float*)d_in[6];
    const float* w2 = (const float*)d_in[7];  const float* b2 = (const float*)d_in[8];
    const float* w3 = (const float*)d_in[9];  const float* b3 = (const float*)d_in[10];
    const float* g0 = (const float*)d_in[11]; const float* be0 = (const float*)d_in[12];
    const float* g1 = (const float*)d_in[13]; const float* be1 = (const float*)d_in[14];
    const float* g2 = (const float*)d_in[15]; const float* be2 = (const float*)d_in[16];
    const float* wlin = (const float*)d_in[17]; const float* blin = (const float*)d_in[18];
    float* out = (float*)d_out;

    const int* src = ei;
    const int* dst = ei + N_EDGES;

    float *hA, *hB;
    __nv_bfloat16 *wth, *wtl;
    void *xh0, *xl0, *xh1, *xl1;
    cudaGetSymbolAddress((void**)&hA, g_hA);
    cudaGetSymbolAddress((void**)&hB, g_hB);
    cudaGetSymbolAddress((void**)&wth, g_Wth);
    cudaGetSymbolAddress((void**)&wtl, g_Wtl);
    cudaGetSymbolAddress(&xh0, g_Xh0_);
    cudaGetSymbolAddress(&xl0, g_Xl0_);
    cudaGetSymbolAddress(&xh1, g_Xh1_);
    cudaGetSymbolAddress(&xl1, g_Xl1_);

    int nbE = (N_EDGES + 255) / 256;
    int nbN = (N_NODES + 255) / 256;

    // dynamic smem: 1024 pad + 2*M*128 (A hi/lo) + 2*3*FOP*128 (B hi/lo)
    const int SM_L0 = 1024 + 2 * 64 * 128 + 2 * 3 * 96 * 128;    // <6,2> 91136
    const int SM_L1 = 1024 + 2 * 64 * 128 + 2 * 3 * 64 * 128;    // <4,2> 66560
    const int SM_L23 = 1024 + 2 * 128 * 128 + 2 * 3 * 32 * 128;  // <4,1> 58368
    typedef void (*gemm_fn)(const __nv_bfloat16*, const __nv_bfloat16*,
                            const __nv_bfloat16*, const __nv_bfloat16*,
                            const float*, float*, uint32_t*, uint32_t*,
                            int, int, int, int, int);
    gemm_fn f62 = k_mma_gemm<6, 2>;
    gemm_fn f42 = k_mma_gemm<4, 2>;
    gemm_fn f41 = k_mma_gemm<4, 1>;
    cudaFuncSetAttribute((const void*)f62, cudaFuncAttributeMaxDynamicSharedMemorySize, SM_L0);
    cudaFuncSetAttribute((const void*)f42, cudaFuncAttributeMaxDynamicSharedMemorySize, SM_L1);
    cudaFuncSetAttribute((const void*)f41, cudaFuncAttributeMaxDynamicSharedMemorySize, SM_L23);

    // CSR + per-node scalers
    k_convx<<<(N_NODES * 32 + 255) / 256, 256>>>(x, (uint32_t*)xh0, (uint32_t*)xl0, N_NODES * 32);
    k_hist<<<nbE, 256>>>(dst);
    k_scanA<<<NB_SCAN, 1024>>>();
    k_scanB<<<NB_SCAN, 1024>>>(batch);
    k_scatter<<<nbE, 256>>>(src, dst);

    const int GB64  = (N_NODES + 63) / 64;
    const int GB128 = (N_NODES + 127) / 128;
    const int AGGB  = (N_NODES * 32 + 255) / 256;

    const int K5P0 = 320;   // F=64
    const int K5P1 = 512;   // F=96
    const int K5P3 = 192;   // F=32

    // Layer 0: 64 -> 96, BN + relu
    k_wsplit<<<(3 * 96 * K5P0 + 255) / 256, 256>>>(w0, 64, 96, 96, K5P0);
    k_agg<64><<<AGGB, 256>>>(x);
    k_mma_gemm<6, 2><<<GB64, 256, SM_L0>>>((__nv_bfloat16*)xh0, (__nv_bfloat16*)xl0,
                                           wth, wtl, b0, hA, 0, 0, 64, 96, K5P0, 0, 1);
    k_bnfin<96><<<1, 96>>>(g0, be0);
    k_bnapply_b16<96><<<(N_NODES * 48 + 255) / 256, 256>>>(hA, (uint32_t*)xh1, (uint32_t*)xl1);

    // Layer 1: 96 -> 64, BN + relu
    k_wsplit<<<(3 * 64 * K5P1 + 255) / 256, 256>>>(w1, 96, 64, 64, K5P1);
    k_agg<96><<<AGGB, 256>>>(hA);
    k_mma_gemm<4, 2><<<GB64, 256, SM_L1>>>((__nv_bfloat16*)xh1, (__nv_bfloat16*)xl1,
                                           wth, wtl, b1, hB, 0, 0, 96, 64, K5P1, 0, 1);
    k_bnfin<64><<<1, 64>>>(g1, be1);
    k_bnapply_b16<64><<<(N_NODES * 32 + 255) / 256, 256>>>(hB, (uint32_t*)xh0, (uint32_t*)xl0);

    // Layer 2: 64 -> 32, relu fused; epilogue also writes bf16 hi/lo for layer 3
    k_wsplit<<<(3 * 32 * K5P0 + 255) / 256, 256>>>(w2, 64, 32, 32, K5P0);
    k_agg<64><<<AGGB, 256>>>(hB);
    k_mma_gemm<4, 1><<<GB128, 256, SM_L23>>>((__nv_bfloat16*)xh0, (__nv_bfloat16*)xl0,
                                             wth, wtl, b2, hA,
                                             (uint32_t*)xh1, (uint32_t*)xl1, 64, 32, K5P0, 1, 0);

    // Layer 3: 32 -> 20, BN (no relu)
    k_wsplit<<<(3 * 32 * K5P3 + 255) / 256, 256>>>(w3, 32, 20, 32, K5P3);
    k_agg<32><<<AGGB, 256>>>(hA);
    k_mma_gemm<4, 1><<<GB128, 256, SM_L23>>>((__nv_bfloat16*)xh1, (__nv_bfloat16*)xl1,
                                             wth, wtl, b3, hB, 0, 0, 32, 20, K5P3, 0, 1);
    k_bnfin<20><<<1, 20>>>(g2, be2);
    k_bnapply<20, false><<<(N_NODES * 20 + 255) / 256, 256>>>(hB);

    // Fused pool + head. Output layout: [softmax out (64x11) | z (64x20)]
    int write_z = (out_size >= 64 * 11 + 64 * 20) ? 1 : 0;
    k_poolfinal<<<N_GRAPH, dim3(32, 8)>>>(hB, wlin, blin, out, out + 64 * 11, write_z);
}